// round 6
// baseline (speedup 1.0000x reference)
#include <cuda_runtime.h>
#include <mma.h>
#include <cstdint>
using namespace nvcuda;

#define Nn 50000
#define Ee 800000
#define Hh 4
#define Dd 128
#define HDd 512
#define Ll 4
#define MPAD 50048   // 391 * 128, pads GEMM M-tiles so epilogue stores are unguarded

#define WSZ (Dd * HDd)          // 65536 per weight matrix
#define NWEIGHT (3 * Ll * WSZ)  // 786432
#define NFEAT (Nn * Dd)         // 6.4M

// dynamic smem layout for gemm: [A0(128x36)][A1][B0(32x132)][B1], floats
#define A_STRIDE 4608           // 128*36
#define B_STRIDE 4224           // 32*132
#define B_BASE   9216           // 2*A_STRIDE
#define SMEM_GEMM ((2 * (A_STRIDE + B_STRIDE)) * 4)   // 70656 bytes

// ---------------- scratch (static device memory; no allocations) ----------------
__device__ __align__(16) float g_feat[(size_t)MPAD * HDd];
__device__ __align__(16) float g_res [(size_t)MPAD * HDd];
__device__ __align__(16) float g_el[Nn * Hh];
__device__ __align__(16) float g_er[Nn * Hh];
__device__ __align__(16) float g_m4 [Nn * Hh];
__device__ __align__(16) float g_iz4[Nn * Hh];
__device__ __align__(16) float g_xA[(size_t)Nn * Dd];
__device__ __align__(16) float g_xB[(size_t)Nn * Dd];
__device__ __align__(16) float g_x0[(size_t)Nn * Dd];     // tf32-rounded features
__device__ __align__(16) float g_wr[NWEIGHT];             // tf32-rounded weights
__device__ int g_deg[Nn];
__device__ int g_rowptr[Nn + 1];
__device__ int g_cursor[Nn];
__device__ int g_csrsrc[Ee];

__device__ __forceinline__ float tf32r(float x) { return wmma::__float_to_tf32(x); }

// ---------------- preamble: round weights+features to tf32, zero deg ----------------
__global__ void k_pre(const float* __restrict__ Wf, const float* __restrict__ Wr,
                      const float* __restrict__ Wn, const float* __restrict__ feats)
{
    int i = blockIdx.x * blockDim.x + threadIdx.x;
    if (i < NFEAT) g_x0[i] = tf32r(feats[i]);
    if (i < Ll * WSZ) {
        g_wr[i]                = tf32r(Wf[i]);
        g_wr[Ll * WSZ + i]     = tf32r(Wr[i]);
        g_wr[2 * Ll * WSZ + i] = tf32r(Wn[i]);
    }
    if (i < Nn) g_deg[i] = 0;
}

__global__ void k_count(const int* __restrict__ dst) {
    int i = blockIdx.x * blockDim.x + threadIdx.x;
    if (i < Ee) atomicAdd(&g_deg[dst[i]], 1);
}

// single-block exclusive scan over g_deg -> g_rowptr (+ cursor init fused)
__global__ void k_scan() {
    __shared__ int sh[1024];
    __shared__ int carry;
    int t = threadIdx.x;
    if (t == 0) { carry = 0; g_rowptr[0] = 0; }
    __syncthreads();
    for (int base = 0; base < Nn; base += 1024) {
        int i = base + t;
        int v = (i < Nn) ? g_deg[i] : 0;
        sh[t] = v;
        __syncthreads();
        #pragma unroll
        for (int off = 1; off < 1024; off <<= 1) {
            int tv = (t >= off) ? sh[t - off] : 0;
            __syncthreads();
            sh[t] += tv;
            __syncthreads();
        }
        int incl = sh[t];
        int c = carry;
        __syncthreads();
        if (i < Nn) {
            g_rowptr[i + 1] = c + incl;
            g_cursor[i] = c + incl - v;
        }
        if (t == 1023) carry = c + incl;
        __syncthreads();
    }
}

__global__ void k_fill(const int* __restrict__ src, const int* __restrict__ dst) {
    int i = blockIdx.x * blockDim.x + threadIdx.x;
    if (i < Ee) {
        int p = atomicAdd(&g_cursor[dst[i]], 1);
        g_csrsrc[p] = src[i];
    }
}

// ---------------- cp.async helper ----------------
__device__ __forceinline__ void cp16(uint32_t dst, const void* src, bool pred) {
    int sz = pred ? 16 : 0;
    asm volatile("cp.async.cg.shared.global [%0], [%1], 16, %2;\n"
                 :: "r"(dst), "l"(src), "r"(sz));
}

// ---------------- tf32 tensor-core GEMM, BK=32, 2-stage ping-pong ----------------
// Inputs MUST already be tf32-rounded. CTA 128x128, 8 warps (2m x 4n), warp 64x32.
// FUSE_LN: TPH must be 1; epilogue does bias+layernorm in-kernel and writes
// guarded rows (no padding needed). Otherwise stores unguarded to padded C.
template<int K, int TPH, int FUSE_LN>
__global__ __launch_bounds__(256, 2) void gemm_tc(
    const float* __restrict__ A,
    const float* __restrict__ B0, const float* __restrict__ B1,
    float* __restrict__ C0, float* __restrict__ C1, int M,
    const float* __restrict__ bn, const float* __restrict__ lng,
    const float* __restrict__ lnb, int doRound)
{
    constexpr int NN = TPH * 128;
    extern __shared__ float sm[];

    const int tid = threadIdx.x;
    const int warp = tid >> 5;
    const int lane = tid & 31;
    const int wm = warp & 1, wn = warp >> 1;
    const int row0 = blockIdx.y * 128;

    int bx = blockIdx.x;
    const float* B = B0;
    float* C = C0;
    if (bx >= TPH) { bx -= TPH; B = B1; C = C1; }
    const int col0 = bx * 128;

    wmma::fragment<wmma::accumulator, 16, 16, 8, float> acc[4][2];
    #pragma unroll
    for (int i = 0; i < 4; i++)
        #pragma unroll
        for (int j = 0; j < 2; j++)
            wmma::fill_fragment(acc[i][j], 0.0f);

    constexpr int KT = K >> 5;

    auto stage = [&](int buf, int k0) {
        float* As = sm + buf * A_STRIDE;
        float* Bs = sm + B_BASE + buf * B_STRIDE;
        #pragma unroll
        for (int p = 0; p < 4; p++) {           // A: 128x32 = 1024 float4
            int c = tid + p * 256;
            int r = c >> 3, q = c & 7;
            int gm = row0 + r;
            const float* srcp = A + (size_t)gm * K + k0 + q * 4;
            uint32_t d = (uint32_t)__cvta_generic_to_shared(&As[r * 36 + q * 4]);
            cp16(d, srcp, gm < M);
        }
        #pragma unroll
        for (int p = 0; p < 4; p++) {           // B: 32x128 = 1024 float4
            int c = tid + p * 256;
            int r = c >> 5, q = c & 31;
            const float* srcp = B + (size_t)(k0 + r) * NN + col0 + q * 4;
            uint32_t d = (uint32_t)__cvta_generic_to_shared(&Bs[r * 132 + q * 4]);
            cp16(d, srcp, true);
        }
        asm volatile("cp.async.commit_group;");
    };

    stage(0, 0);
    for (int kt = 0; kt < KT; kt++) {
        asm volatile("cp.async.wait_group 0;");
        __syncthreads();
        if (kt + 1 < KT) stage((kt + 1) & 1, (kt + 1) << 5);  // overlap next load

        int buf = kt & 1;
        const float* As = sm + buf * A_STRIDE;
        const float* Bs = sm + B_BASE + buf * B_STRIDE;
        #pragma unroll
        for (int kk = 0; kk < 4; kk++) {
            wmma::fragment<wmma::matrix_a, 16, 16, 8, wmma::precision::tf32, wmma::row_major> a[4];
            wmma::fragment<wmma::matrix_b, 16, 16, 8, wmma::precision::tf32, wmma::row_major> b[2];
            #pragma unroll
            for (int i = 0; i < 4; i++)
                wmma::load_matrix_sync(a[i], As + (wm * 64 + i * 16) * 36 + kk * 8, 36);
            #pragma unroll
            for (int j = 0; j < 2; j++)
                wmma::load_matrix_sync(b[j], Bs + (kk * 8) * 132 + wn * 32 + j * 16, 132);
            #pragma unroll
            for (int i = 0; i < 4; i++)
                #pragma unroll
                for (int j = 0; j < 2; j++)
                    wmma::mma_sync(acc[i][j], a[i], b[j], acc[i][j]);
        }
        __syncthreads();
    }

    if (!FUSE_LN) {
        #pragma unroll
        for (int i = 0; i < 4; i++)
            #pragma unroll
            for (int j = 0; j < 2; j++)
                wmma::store_matrix_sync(
                    C + (size_t)(row0 + wm * 64 + i * 16) * NN + col0 + wn * 32 + j * 16,
                    acc[i][j], NN, wmma::mem_row_major);
    } else {
        // fused bias + layernorm epilogue: two 64-row phases through smem
        float* sC = sm;   // 64 x 132 floats = 33.8KB, fits in stage buffers
        float4 bnv = ((const float4*)bn)[lane];
        float4 ggv = ((const float4*)lng)[lane];
        float4 bbv = ((const float4*)lnb)[lane];
        #pragma unroll
        for (int p = 0; p < 2; p++) {
            if (wm == p) {
                #pragma unroll
                for (int i = 0; i < 4; i++)
                    #pragma unroll
                    for (int j = 0; j < 2; j++)
                        wmma::store_matrix_sync(
                            sC + (size_t)(i * 16) * 132 + wn * 32 + j * 16,
                            acc[i][j], 132, wmma::mem_row_major);
            }
            __syncthreads();
            #pragma unroll
            for (int rr = 0; rr < 8; rr++) {
                int lr = warp * 8 + rr;
                int gm = row0 + p * 64 + lr;
                float4 v = *(const float4*)(sC + (size_t)lr * 132 + lane * 4);
                v.x += bnv.x; v.y += bnv.y; v.z += bnv.z; v.w += bnv.w;
                float s = v.x + v.y + v.z + v.w;
                #pragma unroll
                for (int o = 16; o; o >>= 1) s += __shfl_xor_sync(0xffffffffu, s, o);
                float mu = s * (1.f / 128.f);
                float dx = v.x - mu, dy = v.y - mu, dz = v.z - mu, dw = v.w - mu;
                float q = dx * dx + dy * dy + dz * dz + dw * dw;
                #pragma unroll
                for (int o = 16; o; o >>= 1) q += __shfl_xor_sync(0xffffffffu, q, o);
                float rstd = rsqrtf(q * (1.f / 128.f) + 1e-5f);
                float4 o4;
                o4.x = dx * rstd * ggv.x + bbv.x;
                o4.y = dy * rstd * ggv.y + bbv.y;
                o4.z = dz * rstd * ggv.z + bbv.z;
                o4.w = dw * rstd * ggv.w + bbv.w;
                if (doRound) {
                    o4.x = tf32r(o4.x); o4.y = tf32r(o4.y);
                    o4.z = tf32r(o4.z); o4.w = tf32r(o4.w);
                }
                if (gm < M)
                    *(float4*)(C + (size_t)gm * NN + lane * 4) = o4;
            }
            __syncthreads();
        }
    }
}

// ---------------- attention coefficients: el/er = feat . attn ----------------
__global__ __launch_bounds__(128) void k_attn(
    const float* __restrict__ feat,
    const float* __restrict__ al, const float* __restrict__ ar)
{
    int n = blockIdx.x;
    int h = threadIdx.x >> 5, lane = threadIdx.x & 31;
    float4 f = ((const float4*)(feat + (size_t)n * HDd + h * Dd))[lane];
    float4 a = ((const float4*)(al + h * Dd))[lane];
    float4 b = ((const float4*)(ar + h * Dd))[lane];
    float sl = f.x * a.x + f.y * a.y + f.z * a.z + f.w * a.w;
    float sr = f.x * b.x + f.y * b.y + f.z * b.z + f.w * b.w;
    #pragma unroll
    for (int o = 16; o; o >>= 1) {
        sl += __shfl_xor_sync(0xffffffffu, sl, o);
        sr += __shfl_xor_sync(0xffffffffu, sr, o);
    }
    if (lane == 0) {
        g_el[n * Hh + h] = sl;
        g_er[n * Hh + h] = sr;
    }
}

// ---------------- pass A: per-(node,head) softmax max & denominator ----------------
__global__ __launch_bounds__(128) void k_mz() {
    int n = blockIdx.x * 4 + (threadIdx.x >> 5);
    int lane = threadIdx.x & 31;
    if (n >= Nn) return;
    int beg = g_rowptr[n], end = g_rowptr[n + 1];
    float4 er = *(const float4*)(g_er + n * 4);

    float m0 = -1e30f, m1 = -1e30f, m2 = -1e30f, m3 = -1e30f;
    float z0 = 0.f, z1 = 0.f, z2 = 0.f, z3 = 0.f;

    for (int e = beg + lane; e < end; e += 32) {
        int s = g_csrsrc[e];
        float4 el = *(const float4*)(g_el + s * 4);
        float v0 = el.x + er.x; v0 = v0 > 0.f ? v0 : 0.2f * v0;
        float v1 = el.y + er.y; v1 = v1 > 0.f ? v1 : 0.2f * v1;
        float v2 = el.z + er.z; v2 = v2 > 0.f ? v2 : 0.2f * v2;
        float v3 = el.w + er.w; v3 = v3 > 0.f ? v3 : 0.2f * v3;
        float M;
        M = fmaxf(m0, v0); z0 = z0 * __expf(m0 - M) + __expf(v0 - M); m0 = M;
        M = fmaxf(m1, v1); z1 = z1 * __expf(m1 - M) + __expf(v1 - M); m1 = M;
        M = fmaxf(m2, v2); z2 = z2 * __expf(m2 - M) + __expf(v2 - M); m2 = M;
        M = fmaxf(m3, v3); z3 = z3 * __expf(m3 - M) + __expf(v3 - M); m3 = M;
    }
    #pragma unroll
    for (int o = 16; o; o >>= 1) {
        float mo, zo, M;
        mo = __shfl_xor_sync(0xffffffffu, m0, o); zo = __shfl_xor_sync(0xffffffffu, z0, o);
        M = fmaxf(m0, mo); z0 = z0 * __expf(m0 - M) + zo * __expf(mo - M); m0 = M;
        mo = __shfl_xor_sync(0xffffffffu, m1, o); zo = __shfl_xor_sync(0xffffffffu, z1, o);
        M = fmaxf(m1, mo); z1 = z1 * __expf(m1 - M) + zo * __expf(mo - M); m1 = M;
        mo = __shfl_xor_sync(0xffffffffu, m2, o); zo = __shfl_xor_sync(0xffffffffu, z2, o);
        M = fmaxf(m2, mo); z2 = z2 * __expf(m2 - M) + zo * __expf(mo - M); m2 = M;
        mo = __shfl_xor_sync(0xffffffffu, m3, o); zo = __shfl_xor_sync(0xffffffffu, z3, o);
        M = fmaxf(m3, mo); z3 = z3 * __expf(m3 - M) + zo * __expf(mo - M); m3 = M;
    }
    if (lane == 0) {
        *(float4*)(g_m4 + n * 4) = make_float4(m0, m1, m2, m3);
        *(float4*)(g_iz4 + n * 4) = make_float4(
            1.f / fmaxf(z0, 1e-20f), 1.f / fmaxf(z1, 1e-20f),
            1.f / fmaxf(z2, 1e-20f), 1.f / fmaxf(z3, 1e-20f));
    }
}

// ---------------- pass B: weighted accumulate + residual + bias + leaky ------------
// output rounded to tf32 (feeds next GEMM only)
__global__ __launch_bounds__(128) void k_agg(const float* __restrict__ bgat) {
    int n = blockIdx.x;
    int h = threadIdx.x >> 5, lane = threadIdx.x & 31;
    int beg = g_rowptr[n], end = g_rowptr[n + 1];
    float ern = g_er[n * 4 + h];
    float m   = g_m4[n * 4 + h];
    float iz  = g_iz4[n * 4 + h];

    float4 acc = make_float4(0.f, 0.f, 0.f, 0.f);
    int e = beg;
    for (; e + 4 <= end; e += 4) {
        int s0 = g_csrsrc[e + 0];
        int s1 = g_csrsrc[e + 1];
        int s2 = g_csrsrc[e + 2];
        int s3 = g_csrsrc[e + 3];
        float v0 = g_el[s0 * 4 + h] + ern;
        float v1 = g_el[s1 * 4 + h] + ern;
        float v2 = g_el[s2 * 4 + h] + ern;
        float v3 = g_el[s3 * 4 + h] + ern;
        float4 f0 = *(const float4*)(g_feat + (size_t)s0 * HDd + h * Dd + lane * 4);
        float4 f1 = *(const float4*)(g_feat + (size_t)s1 * HDd + h * Dd + lane * 4);
        float4 f2 = *(const float4*)(g_feat + (size_t)s2 * HDd + h * Dd + lane * 4);
        float4 f3 = *(const float4*)(g_feat + (size_t)s3 * HDd + h * Dd + lane * 4);
        v0 = v0 > 0.f ? v0 : 0.2f * v0;
        v1 = v1 > 0.f ? v1 : 0.2f * v1;
        v2 = v2 > 0.f ? v2 : 0.2f * v2;
        v3 = v3 > 0.f ? v3 : 0.2f * v3;
        float w0 = __expf(v0 - m), w1 = __expf(v1 - m);
        float w2 = __expf(v2 - m), w3 = __expf(v3 - m);
        acc.x += w0 * f0.x + w1 * f1.x + w2 * f2.x + w3 * f3.x;
        acc.y += w0 * f0.y + w1 * f1.y + w2 * f2.y + w3 * f3.y;
        acc.z += w0 * f0.z + w1 * f1.z + w2 * f2.z + w3 * f3.z;
        acc.w += w0 * f0.w + w1 * f1.w + w2 * f2.w + w3 * f3.w;
    }
    for (; e < end; e++) {
        int s = g_csrsrc[e];
        float v = g_el[s * 4 + h] + ern;
        v = v > 0.f ? v : 0.2f * v;
        float w = __expf(v - m);
        float4 f = *(const float4*)(g_feat + (size_t)s * HDd + h * Dd + lane * 4);
        acc.x += w * f.x; acc.y += w * f.y; acc.z += w * f.z; acc.w += w * f.w;
    }

    float* rp = g_res + (size_t)n * HDd + h * Dd + lane * 4;
    float4 r = *(float4*)rp;
    float4 bg = *(const float4*)(bgat + h * Dd + lane * 4);
    float4 o;
    o.x = acc.x * iz + r.x + bg.x;
    o.y = acc.y * iz + r.y + bg.y;
    o.z = acc.z * iz + r.z + bg.z;
    o.w = acc.w * iz + r.w + bg.w;
    o.x = o.x > 0.f ? o.x : 0.01f * o.x;
    o.y = o.y > 0.f ? o.y : 0.01f * o.y;
    o.z = o.z > 0.f ? o.z : 0.01f * o.z;
    o.w = o.w > 0.f ? o.w : 0.01f * o.w;
    o.x = tf32r(o.x); o.y = tf32r(o.y); o.z = tf32r(o.z); o.w = tf32r(o.w);
    *(float4*)rp = o;
}

// ---------------- launch ----------------
extern "C" void kernel_launch(void* const* d_in, const int* in_sizes, int n_in,
                              void* d_out, int out_size)
{
    const float* features = (const float*)d_in[0];
    const int*   src      = (const int*)  d_in[1];
    const int*   dst      = (const int*)  d_in[2];
    const float* W_fc     = (const float*)d_in[3];
    const float* attn_l   = (const float*)d_in[4];
    const float* attn_r   = (const float*)d_in[5];
    const float* W_res    = (const float*)d_in[6];
    const float* b_gat    = (const float*)d_in[7];
    const float* W_nrm    = (const float*)d_in[8];
    const float* b_nrm    = (const float*)d_in[9];
    const float* ln_g     = (const float*)d_in[10];
    const float* ln_b     = (const float*)d_in[11];
    float* out = (float*)d_out;

    float *feat, *res, *xA, *xB, *x0, *wr;
    cudaGetSymbolAddress((void**)&feat, g_feat);
    cudaGetSymbolAddress((void**)&res,  g_res);
    cudaGetSymbolAddress((void**)&xA,   g_xA);
    cudaGetSymbolAddress((void**)&xB,   g_xB);
    cudaGetSymbolAddress((void**)&x0,   g_x0);
    cudaGetSymbolAddress((void**)&wr,   g_wr);

    static int smemSet = 0;
    if (!smemSet) {
        cudaFuncSetAttribute(gemm_tc<Dd, HDd / 128, 0>,
                             cudaFuncAttributeMaxDynamicSharedMemorySize, SMEM_GEMM);
        cudaFuncSetAttribute(gemm_tc<HDd, 1, 1>,
                             cudaFuncAttributeMaxDynamicSharedMemorySize, SMEM_GEMM);
        smemSet = 1;
    }

    // preamble (rounding + zero), count, scan -> dual GEMM stays launch #4 for ncu
    k_pre<<<(NFEAT + 255) / 256, 256>>>(W_fc, W_res, W_nrm, features);
    k_count<<<(Ee + 255) / 256, 256>>>(dst);
    k_scan<<<1, 1024>>>();

    const int gy = (Nn + 127) / 128;   // 391

    const float* xin = x0;
    for (int l = 0; l < Ll; l++) {
        const float* Wf = wr + (size_t)l * WSZ;
        const float* Wr = wr + (size_t)(Ll + l) * WSZ;
        const float* Wn = wr + (size_t)(2 * Ll + l) * WSZ;

        // fused: feat = xin@Wf ; res = xin@Wr (same A), K=128, N=512 each
        dim3 g1(2 * (HDd / 128), gy);
        gemm_tc<Dd, HDd / 128, 0><<<g1, 256, SMEM_GEMM>>>(
            xin, Wf, Wr, feat, res, Nn, nullptr, nullptr, nullptr, 0);

        if (l == 0) k_fill<<<(Ee + 255) / 256, 256>>>(src, dst);

        k_attn<<<Nn, 128>>>(feat, attn_l + l * Hh * Dd, attn_r + l * Hh * Dd);
        k_mz<<<(Nn + 3) / 4, 128>>>();
        k_agg<<<Nn, 128>>>(b_gat + l * HDd);

        // xout = layernorm(res @ Wn + b_nrm), fused epilogue, K=512, N=128
        float* xout = (l == Ll - 1) ? out : ((l & 1) ? xB : xA);
        dim3 g2(1, gy);
        gemm_tc<HDd, 1, 1><<<g2, 256, SMEM_GEMM>>>(
            res, Wn, nullptr, xout, nullptr, Nn,
            b_nrm + l * Dd, ln_g + l * Dd, ln_b + l * Dd, l != Ll - 1);
        xin = xout;
    }
}

// round 7
// speedup vs baseline: 1.0401x; 1.0401x over previous
#include <cuda_runtime.h>
#include <mma.h>
#include <cstdint>
using namespace nvcuda;

#define Nn 50000
#define Ee 800000
#define Hh 4
#define Dd 128
#define HDd 512
#define Ll 4
#define MPAD 50048   // 391 * 128, pads GEMM M-tiles so epilogue stores are unguarded

#define WSZ (Dd * HDd)          // 65536 per weight matrix
#define NWEIGHT (3 * Ll * WSZ)  // 786432
#define NFEAT (Nn * Dd)         // 6.4M

// static smem pool (floats): 4 A bufs (128x12) + 4 B bufs (8x132) = 10368 floats
// epilogue reuses it as a 64x132 tile (8448 floats)
#define ASTRIDE 1536            // 128*12
#define BBASE   6144            // 4*ASTRIDE
#define BSTRIDE 1056            // 8*132
#define SMPOOL  10368

// ---------------- scratch (static device memory; no allocations) ----------------
__device__ __align__(16) float g_feat[(size_t)MPAD * HDd];
__device__ __align__(16) float g_res [(size_t)MPAD * HDd];
__device__ __align__(16) float g_el[Nn * Hh];
__device__ __align__(16) float g_er[Nn * Hh];
__device__ __align__(16) float g_m4 [Nn * Hh];
__device__ __align__(16) float g_iz4[Nn * Hh];
__device__ __align__(16) float g_xA[(size_t)Nn * Dd];
__device__ __align__(16) float g_xB[(size_t)Nn * Dd];
__device__ __align__(16) float g_x0[(size_t)Nn * Dd];     // tf32-rounded features
__device__ __align__(16) float g_wr[NWEIGHT];             // tf32-rounded weights
__device__ int g_deg[Nn];
__device__ int g_rowptr[Nn + 1];
__device__ int g_cursor[Nn];
__device__ int g_csrsrc[Ee];

__device__ __forceinline__ float tf32r(float x) { return wmma::__float_to_tf32(x); }

// ---------------- preamble: round weights+features to tf32, zero deg ----------------
__global__ void k_pre(const float* __restrict__ Wf, const float* __restrict__ Wr,
                      const float* __restrict__ Wn, const float* __restrict__ feats)
{
    int i = blockIdx.x * blockDim.x + threadIdx.x;
    if (i < NFEAT) g_x0[i] = tf32r(feats[i]);
    if (i < Ll * WSZ) {
        g_wr[i]                = tf32r(Wf[i]);
        g_wr[Ll * WSZ + i]     = tf32r(Wr[i]);
        g_wr[2 * Ll * WSZ + i] = tf32r(Wn[i]);
    }
    if (i < Nn) g_deg[i] = 0;
}

__global__ void k_count(const int* __restrict__ dst) {
    int i = blockIdx.x * blockDim.x + threadIdx.x;
    if (i < Ee) atomicAdd(&g_deg[dst[i]], 1);
}

// single-block exclusive scan over g_deg -> g_rowptr (+ cursor init fused)
__global__ void k_scan() {
    __shared__ int sh[1024];
    __shared__ int carry;
    int t = threadIdx.x;
    if (t == 0) { carry = 0; g_rowptr[0] = 0; }
    __syncthreads();
    for (int base = 0; base < Nn; base += 1024) {
        int i = base + t;
        int v = (i < Nn) ? g_deg[i] : 0;
        sh[t] = v;
        __syncthreads();
        #pragma unroll
        for (int off = 1; off < 1024; off <<= 1) {
            int tv = (t >= off) ? sh[t - off] : 0;
            __syncthreads();
            sh[t] += tv;
            __syncthreads();
        }
        int incl = sh[t];
        int c = carry;
        __syncthreads();
        if (i < Nn) {
            g_rowptr[i + 1] = c + incl;
            g_cursor[i] = c + incl - v;
        }
        if (t == 1023) carry = c + incl;
        __syncthreads();
    }
}

__global__ void k_fill(const int* __restrict__ src, const int* __restrict__ dst) {
    int i = blockIdx.x * blockDim.x + threadIdx.x;
    if (i < Ee) {
        int p = atomicAdd(&g_cursor[dst[i]], 1);
        g_csrsrc[p] = src[i];
    }
}

// ---------------- cp.async helper ----------------
__device__ __forceinline__ void cp16(uint32_t dst, const void* src, bool pred) {
    int sz = pred ? 16 : 0;
    asm volatile("cp.async.cg.shared.global [%0], [%1], 16, %2;\n"
                 :: "r"(dst), "l"(src), "r"(sz));
}

// ---------------- tf32 tensor-core GEMM, BK=8, 4-stage ring (R5 mainloop) ----------
// MODE 0: dual-output plain store (feat half also computes attn el/er in epilogue
//         when attn pointers non-null; head h == column tile index bx)
// MODE 1: TPH==1, fused bias+layernorm epilogue, guarded stores
template<int K, int TPH, int MODE>
__global__ __launch_bounds__(256) void gemm_tc(
    const float* __restrict__ A,
    const float* __restrict__ B0, const float* __restrict__ B1,
    float* __restrict__ C0, float* __restrict__ C1, int M,
    const float* __restrict__ p0, const float* __restrict__ p1,
    const float* __restrict__ p2, int doRound)
{
    constexpr int NN = TPH * 128;
    __shared__ float smbuf[SMPOOL];

    const int tid = threadIdx.x;
    const int warp = tid >> 5;
    const int lane = tid & 31;
    const int wm = warp & 1, wn = warp >> 1;
    const int row0 = blockIdx.y * 128;

    int bx = blockIdx.x;
    bool isFeatHalf = (bx < TPH);
    const float* B = B0;
    float* C = C0;
    if (!isFeatHalf) { bx -= TPH; B = B1; C = C1; }
    const int col0 = bx * 128;

    wmma::fragment<wmma::accumulator, 16, 16, 8, float> acc[4][2];
    #pragma unroll
    for (int i = 0; i < 4; i++)
        #pragma unroll
        for (int j = 0; j < 2; j++)
            wmma::fill_fragment(acc[i][j], 0.0f);

    constexpr int KT = K >> 3;

    auto stage = [&](int buf, int k0) {
        float* As = smbuf + buf * ASTRIDE;
        float* Bs = smbuf + BBASE + buf * BSTRIDE;
        {
            int r = tid >> 1, q = tid & 1;
            int gm = row0 + r;
            const float* srcp = A + (size_t)gm * K + k0 + q * 4;
            uint32_t d = (uint32_t)__cvta_generic_to_shared(&As[r * 12 + q * 4]);
            cp16(d, srcp, gm < M);
        }
        {
            int r = tid >> 5, nq = tid & 31;
            const float* srcp = B + (size_t)(k0 + r) * NN + col0 + nq * 4;
            uint32_t d = (uint32_t)__cvta_generic_to_shared(&Bs[r * 132 + nq * 4]);
            cp16(d, srcp, true);
        }
        asm volatile("cp.async.commit_group;");
    };

    stage(0, 0);
    stage(1, 8);
    stage(2, 16);

    #pragma unroll 4
    for (int kt = 0; kt < KT; kt++) {
        if (kt + 3 < KT) asm volatile("cp.async.wait_group 2;");
        else             asm volatile("cp.async.wait_group 0;");
        __syncthreads();

        int buf = kt & 3;
        const float* As = smbuf + buf * ASTRIDE;
        const float* Bs = smbuf + BBASE + buf * BSTRIDE;
        wmma::fragment<wmma::matrix_a, 16, 16, 8, wmma::precision::tf32, wmma::row_major> a[4];
        wmma::fragment<wmma::matrix_b, 16, 16, 8, wmma::precision::tf32, wmma::row_major> b[2];
        #pragma unroll
        for (int i = 0; i < 4; i++)
            wmma::load_matrix_sync(a[i], As + (wm * 64 + i * 16) * 12, 12);
        #pragma unroll
        for (int j = 0; j < 2; j++)
            wmma::load_matrix_sync(b[j], Bs + wn * 32 + j * 16, 132);
        #pragma unroll
        for (int i = 0; i < 4; i++)
            #pragma unroll
            for (int j = 0; j < 2; j++)
                wmma::mma_sync(acc[i][j], a[i], b[j], acc[i][j]);

        if (kt + 3 < KT) stage((kt + 3) & 3, (kt + 3) << 3);
    }

    if (MODE == 0) {
        // plain unguarded store (C padded to MPAD)
        #pragma unroll
        for (int i = 0; i < 4; i++)
            #pragma unroll
            for (int j = 0; j < 2; j++)
                wmma::store_matrix_sync(
                    C + (size_t)(row0 + wm * 64 + i * 16) * NN + col0 + wn * 32 + j * 16,
                    acc[i][j], NN, wmma::mem_row_major);

        // fused attention-coefficient epilogue (feat half only; head h == bx)
        if (isFeatHalf && p0 != nullptr) {
            float* sC = smbuf;   // 64 x 132
            float4 alv = *(const float4*)(p0 + col0 + lane * 4);
            float4 arv = *(const float4*)(p1 + col0 + lane * 4);
            __syncthreads();     // mainloop smem reads done before overwrite
            #pragma unroll
            for (int p = 0; p < 2; p++) {
                if (wm == p) {
                    #pragma unroll
                    for (int i = 0; i < 4; i++)
                        #pragma unroll
                        for (int j = 0; j < 2; j++)
                            wmma::store_matrix_sync(
                                sC + (size_t)(i * 16) * 132 + wn * 32 + j * 16,
                                acc[i][j], 132, wmma::mem_row_major);
                }
                __syncthreads();
                #pragma unroll
                for (int rr = 0; rr < 8; rr++) {
                    int lr = warp * 8 + rr;
                    int gm = row0 + p * 64 + lr;
                    float4 v = *(const float4*)(sC + (size_t)lr * 132 + lane * 4);
                    float sl = v.x * alv.x + v.y * alv.y + v.z * alv.z + v.w * alv.w;
                    float sr = v.x * arv.x + v.y * arv.y + v.z * arv.z + v.w * arv.w;
                    #pragma unroll
                    for (int o = 16; o; o >>= 1) {
                        sl += __shfl_xor_sync(0xffffffffu, sl, o);
                        sr += __shfl_xor_sync(0xffffffffu, sr, o);
                    }
                    if (lane == 0 && gm < M) {
                        g_el[gm * Hh + bx] = sl;
                        g_er[gm * Hh + bx] = sr;
                    }
                }
                __syncthreads();
            }
        }
    } else {
        // fused bias + layernorm epilogue: two 64-row phases through smem
        float* sC = smbuf;
        float4 bnv = ((const float4*)p0)[lane];
        float4 ggv = ((const float4*)p1)[lane];
        float4 bbv = ((const float4*)p2)[lane];
        #pragma unroll
        for (int p = 0; p < 2; p++) {
            if (wm == p) {
                #pragma unroll
                for (int i = 0; i < 4; i++)
                    #pragma unroll
                    for (int j = 0; j < 2; j++)
                        wmma::store_matrix_sync(
                            sC + (size_t)(i * 16) * 132 + wn * 32 + j * 16,
                            acc[i][j], 132, wmma::mem_row_major);
            }
            __syncthreads();
            #pragma unroll
            for (int rr = 0; rr < 8; rr++) {
                int lr = warp * 8 + rr;
                int gm = row0 + p * 64 + lr;
                float4 v = *(const float4*)(sC + (size_t)lr * 132 + lane * 4);
                v.x += bnv.x; v.y += bnv.y; v.z += bnv.z; v.w += bnv.w;
                float s = v.x + v.y + v.z + v.w;
                #pragma unroll
                for (int o = 16; o; o >>= 1) s += __shfl_xor_sync(0xffffffffu, s, o);
                float mu = s * (1.f / 128.f);
                float dx = v.x - mu, dy = v.y - mu, dz = v.z - mu, dw = v.w - mu;
                float q = dx * dx + dy * dy + dz * dz + dw * dw;
                #pragma unroll
                for (int o = 16; o; o >>= 1) q += __shfl_xor_sync(0xffffffffu, q, o);
                float rstd = rsqrtf(q * (1.f / 128.f) + 1e-5f);
                float4 o4;
                o4.x = dx * rstd * ggv.x + bbv.x;
                o4.y = dy * rstd * ggv.y + bbv.y;
                o4.z = dz * rstd * ggv.z + bbv.z;
                o4.w = dw * rstd * ggv.w + bbv.w;
                if (doRound) {
                    o4.x = tf32r(o4.x); o4.y = tf32r(o4.y);
                    o4.z = tf32r(o4.z); o4.w = tf32r(o4.w);
                }
                if (gm < M)
                    *(float4*)(C + (size_t)gm * NN + lane * 4) = o4;
            }
            __syncthreads();
        }
    }
}

// ---------------- pass A: per-(node,head) softmax max & denominator ----------------
__global__ __launch_bounds__(128) void k_mz() {
    int n = blockIdx.x * 4 + (threadIdx.x >> 5);
    int lane = threadIdx.x & 31;
    if (n >= Nn) return;
    int beg = g_rowptr[n], end = g_rowptr[n + 1];
    float4 er = *(const float4*)(g_er + n * 4);

    float m0 = -1e30f, m1 = -1e30f, m2 = -1e30f, m3 = -1e30f;
    float z0 = 0.f, z1 = 0.f, z2 = 0.f, z3 = 0.f;

    for (int e = beg + lane; e < end; e += 32) {
        int s = g_csrsrc[e];
        float4 el = *(const float4*)(g_el + s * 4);
        float v0 = el.x + er.x; v0 = v0 > 0.f ? v0 : 0.2f * v0;
        float v1 = el.y + er.y; v1 = v1 > 0.f ? v1 : 0.2f * v1;
        float v2 = el.z + er.z; v2 = v2 > 0.f ? v2 : 0.2f * v2;
        float v3 = el.w + er.w; v3 = v3 > 0.f ? v3 : 0.2f * v3;
        float M;
        M = fmaxf(m0, v0); z0 = z0 * __expf(m0 - M) + __expf(v0 - M); m0 = M;
        M = fmaxf(m1, v1); z1 = z1 * __expf(m1 - M) + __expf(v1 - M); m1 = M;
        M = fmaxf(m2, v2); z2 = z2 * __expf(m2 - M) + __expf(v2 - M); m2 = M;
        M = fmaxf(m3, v3); z3 = z3 * __expf(m3 - M) + __expf(v3 - M); m3 = M;
    }
    #pragma unroll
    for (int o = 16; o; o >>= 1) {
        float mo, zo, M;
        mo = __shfl_xor_sync(0xffffffffu, m0, o); zo = __shfl_xor_sync(0xffffffffu, z0, o);
        M = fmaxf(m0, mo); z0 = z0 * __expf(m0 - M) + zo * __expf(mo - M); m0 = M;
        mo = __shfl_xor_sync(0xffffffffu, m1, o); zo = __shfl_xor_sync(0xffffffffu, z1, o);
        M = fmaxf(m1, mo); z1 = z1 * __expf(m1 - M) + zo * __expf(mo - M); m1 = M;
        mo = __shfl_xor_sync(0xffffffffu, m2, o); zo = __shfl_xor_sync(0xffffffffu, z2, o);
        M = fmaxf(m2, mo); z2 = z2 * __expf(m2 - M) + zo * __expf(mo - M); m2 = M;
        mo = __shfl_xor_sync(0xffffffffu, m3, o); zo = __shfl_xor_sync(0xffffffffu, z3, o);
        M = fmaxf(m3, mo); z3 = z3 * __expf(m3 - M) + zo * __expf(mo - M); m3 = M;
    }
    if (lane == 0) {
        *(float4*)(g_m4 + n * 4) = make_float4(m0, m1, m2, m3);
        *(float4*)(g_iz4 + n * 4) = make_float4(
            1.f / fmaxf(z0, 1e-20f), 1.f / fmaxf(z1, 1e-20f),
            1.f / fmaxf(z2, 1e-20f), 1.f / fmaxf(z3, 1e-20f));
    }
}

// ---------------- pass B: weighted accumulate + residual + bias + leaky ------------
__global__ __launch_bounds__(128) void k_agg(const float* __restrict__ bgat) {
    int n = blockIdx.x;
    int h = threadIdx.x >> 5, lane = threadIdx.x & 31;
    int beg = g_rowptr[n], end = g_rowptr[n + 1];
    float ern = g_er[n * 4 + h];
    float m   = g_m4[n * 4 + h];
    float iz  = g_iz4[n * 4 + h];

    float4 acc = make_float4(0.f, 0.f, 0.f, 0.f);
    int e = beg;
    for (; e + 4 <= end; e += 4) {
        int s0 = g_csrsrc[e + 0];
        int s1 = g_csrsrc[e + 1];
        int s2 = g_csrsrc[e + 2];
        int s3 = g_csrsrc[e + 3];
        float v0 = g_el[s0 * 4 + h] + ern;
        float v1 = g_el[s1 * 4 + h] + ern;
        float v2 = g_el[s2 * 4 + h] + ern;
        float v3 = g_el[s3 * 4 + h] + ern;
        float4 f0 = *(const float4*)(g_feat + (size_t)s0 * HDd + h * Dd + lane * 4);
        float4 f1 = *(const float4*)(g_feat + (size_t)s1 * HDd + h * Dd + lane * 4);
        float4 f2 = *(const float4*)(g_feat + (size_t)s2 * HDd + h * Dd + lane * 4);
        float4 f3 = *(const float4*)(g_feat + (size_t)s3 * HDd + h * Dd + lane * 4);
        v0 = v0 > 0.f ? v0 : 0.2f * v0;
        v1 = v1 > 0.f ? v1 : 0.2f * v1;
        v2 = v2 > 0.f ? v2 : 0.2f * v2;
        v3 = v3 > 0.f ? v3 : 0.2f * v3;
        float w0 = __expf(v0 - m), w1 = __expf(v1 - m);
        float w2 = __expf(v2 - m), w3 = __expf(v3 - m);
        acc.x += w0 * f0.x + w1 * f1.x + w2 * f2.x + w3 * f3.x;
        acc.y += w0 * f0.y + w1 * f1.y + w2 * f2.y + w3 * f3.y;
        acc.z += w0 * f0.z + w1 * f1.z + w2 * f2.z + w3 * f3.z;
        acc.w += w0 * f0.w + w1 * f1.w + w2 * f2.w + w3 * f3.w;
    }
    for (; e < end; e++) {
        int s = g_csrsrc[e];
        float v = g_el[s * 4 + h] + ern;
        v = v > 0.f ? v : 0.2f * v;
        float w = __expf(v - m);
        float4 f = *(const float4*)(g_feat + (size_t)s * HDd + h * Dd + lane * 4);
        acc.x += w * f.x; acc.y += w * f.y; acc.z += w * f.z; acc.w += w * f.w;
    }

    float* rp = g_res + (size_t)n * HDd + h * Dd + lane * 4;
    float4 r = *(float4*)rp;
    float4 bg = *(const float4*)(bgat + h * Dd + lane * 4);
    float4 o;
    o.x = acc.x * iz + r.x + bg.x;
    o.y = acc.y * iz + r.y + bg.y;
    o.z = acc.z * iz + r.z + bg.z;
    o.w = acc.w * iz + r.w + bg.w;
    o.x = o.x > 0.f ? o.x : 0.01f * o.x;
    o.y = o.y > 0.f ? o.y : 0.01f * o.y;
    o.z = o.z > 0.f ? o.z : 0.01f * o.z;
    o.w = o.w > 0.f ? o.w : 0.01f * o.w;
    o.x = tf32r(o.x); o.y = tf32r(o.y); o.z = tf32r(o.z); o.w = tf32r(o.w);
    *(float4*)rp = o;
}

// ---------------- launch ----------------
extern "C" void kernel_launch(void* const* d_in, const int* in_sizes, int n_in,
                              void* d_out, int out_size)
{
    const float* features = (const float*)d_in[0];
    const int*   src      = (const int*)  d_in[1];
    const int*   dst      = (const int*)  d_in[2];
    const float* W_fc     = (const float*)d_in[3];
    const float* attn_l   = (const float*)d_in[4];
    const float* attn_r   = (const float*)d_in[5];
    const float* W_res    = (const float*)d_in[6];
    const float* b_gat    = (const float*)d_in[7];
    const float* W_nrm    = (const float*)d_in[8];
    const float* b_nrm    = (const float*)d_in[9];
    const float* ln_g     = (const float*)d_in[10];
    const float* ln_b     = (const float*)d_in[11];
    float* out = (float*)d_out;

    float *feat, *res, *xA, *xB, *x0, *wr;
    cudaGetSymbolAddress((void**)&feat, g_feat);
    cudaGetSymbolAddress((void**)&res,  g_res);
    cudaGetSymbolAddress((void**)&xA,   g_xA);
    cudaGetSymbolAddress((void**)&xB,   g_xB);
    cudaGetSymbolAddress((void**)&x0,   g_x0);
    cudaGetSymbolAddress((void**)&wr,   g_wr);

    // preamble (rounding + zero), count, scan -> dual GEMM is launch #4 for ncu
    k_pre<<<(NFEAT + 255) / 256, 256>>>(W_fc, W_res, W_nrm, features);
    k_count<<<(Ee + 255) / 256, 256>>>(dst);
    k_scan<<<1, 1024>>>();

    const int gy = (Nn + 127) / 128;   // 391

    const float* xin = x0;
    for (int l = 0; l < Ll; l++) {
        const float* Wf = wr + (size_t)l * WSZ;
        const float* Wr = wr + (size_t)(Ll + l) * WSZ;
        const float* Wn = wr + (size_t)(2 * Ll + l) * WSZ;

        // fused: feat = xin@Wf (+ el/er in epilogue) ; res = xin@Wr
        dim3 g1(2 * (HDd / 128), gy);
        gemm_tc<Dd, HDd / 128, 0><<<g1, 256>>>(
            xin, Wf, Wr, feat, res, Nn,
            attn_l + l * Hh * Dd, attn_r + l * Hh * Dd, nullptr, 0);

        if (l == 0) k_fill<<<(Ee + 255) / 256, 256>>>(src, dst);

        k_mz<<<(Nn + 3) / 4, 128>>>();
        k_agg<<<Nn, 128>>>(b_gat + l * HDd);

        // xout = layernorm(res @ Wn + b_nrm), fused LN epilogue
        float* xout = (l == Ll - 1) ? out : ((l & 1) ? xB : xA);
        dim3 g2(1, gy);
        gemm_tc<HDd, 1, 1><<<g2, 256>>>(
            res, Wn, nullptr, xout, nullptr, Nn,
            b_nrm + l * Dd, ln_g + l * Dd, ln_b + l * Dd, l != Ll - 1);
        xin = xout;
    }
}

// round 8
// speedup vs baseline: 1.1336x; 1.0899x over previous
#include <cuda_runtime.h>
#include <mma.h>
#include <cstdint>
using namespace nvcuda;

#define Nn 50000
#define Ee 800000
#define Hh 4
#define Dd 128
#define HDd 512
#define Ll 4
#define MPAD 50048   // 391 * 128, pads GEMM M-tiles so epilogue stores are unguarded

#define WSZ (Dd * HDd)          // 65536 per weight matrix
#define NWEIGHT (3 * Ll * WSZ)  // 786432
#define NFEAT (Nn * Dd)         // 6.4M

// dynamic smem (floats): 4 A bufs (128x20) + 4 B bufs (16x132)
#define ASTRIDE 2560            // 128*20
#define BBASE   10240           // 4*ASTRIDE
#define BSTRIDE 2112            // 16*132
#define SMPOOL  18688           // floats
#define SMBYTES (SMPOOL * 4)    // 74752 bytes

// ---------------- scratch (static device memory; no allocations) ----------------
__device__ __align__(16) float g_feat[(size_t)MPAD * HDd];
__device__ __align__(16) float g_res [(size_t)MPAD * HDd];
__device__ __align__(16) float g_el[Nn * Hh];
__device__ __align__(16) float g_er[Nn * Hh];
__device__ __align__(16) float g_xA[(size_t)Nn * Dd];
__device__ __align__(16) float g_xB[(size_t)Nn * Dd];
__device__ __align__(16) float g_x0[(size_t)Nn * Dd];     // tf32-rounded features
__device__ __align__(16) float g_wr[NWEIGHT];             // tf32-rounded weights
__device__ int g_deg[Nn];
__device__ int g_rowptr[Nn + 1];
__device__ int g_cursor[Nn];
__device__ int g_csrsrc[Ee];

__device__ __forceinline__ float tf32r(float x) { return wmma::__float_to_tf32(x); }

// ---------------- preamble: round weights+features to tf32, zero deg ----------------
__global__ void k_pre(const float* __restrict__ Wf, const float* __restrict__ Wr,
                      const float* __restrict__ Wn, const float* __restrict__ feats)
{
    int i = blockIdx.x * blockDim.x + threadIdx.x;
    if (i < NFEAT) g_x0[i] = tf32r(feats[i]);
    if (i < Ll * WSZ) {
        g_wr[i]                = tf32r(Wf[i]);
        g_wr[Ll * WSZ + i]     = tf32r(Wr[i]);
        g_wr[2 * Ll * WSZ + i] = tf32r(Wn[i]);
    }
    if (i < Nn) g_deg[i] = 0;
}

__global__ void k_count(const int* __restrict__ dst) {
    int i = blockIdx.x * blockDim.x + threadIdx.x;
    if (i < Ee) atomicAdd(&g_deg[dst[i]], 1);
}

// single-block exclusive scan over g_deg -> g_rowptr (+ cursor init fused)
__global__ void k_scan() {
    __shared__ int sh[1024];
    __shared__ int carry;
    int t = threadIdx.x;
    if (t == 0) { carry = 0; g_rowptr[0] = 0; }
    __syncthreads();
    for (int base = 0; base < Nn; base += 1024) {
        int i = base + t;
        int v = (i < Nn) ? g_deg[i] : 0;
        sh[t] = v;
        __syncthreads();
        #pragma unroll
        for (int off = 1; off < 1024; off <<= 1) {
            int tv = (t >= off) ? sh[t - off] : 0;
            __syncthreads();
            sh[t] += tv;
            __syncthreads();
        }
        int incl = sh[t];
        int c = carry;
        __syncthreads();
        if (i < Nn) {
            g_rowptr[i + 1] = c + incl;
            g_cursor[i] = c + incl - v;
        }
        if (t == 1023) carry = c + incl;
        __syncthreads();
    }
}

__global__ void k_fill(const int* __restrict__ src, const int* __restrict__ dst) {
    int i = blockIdx.x * blockDim.x + threadIdx.x;
    if (i < Ee) {
        int p = atomicAdd(&g_cursor[dst[i]], 1);
        g_csrsrc[p] = src[i];
    }
}

// ---------------- cp.async helper ----------------
__device__ __forceinline__ void cp16(uint32_t dst, const void* src, bool pred) {
    int sz = pred ? 16 : 0;
    asm volatile("cp.async.cg.shared.global [%0], [%1], 16, %2;\n"
                 :: "r"(dst), "l"(src), "r"(sz));
}

// ---------------- tf32 tensor-core GEMM, BK=16, 4-stage ring ----------------------
// MODE 0: dual-output plain store (feat half also computes attn el/er in epilogue
//         when attn pointers non-null; head h == column tile index bx)
// MODE 1: TPH==1, fused bias+layernorm epilogue, guarded stores
template<int K, int TPH, int MODE>
__global__ __launch_bounds__(256) void gemm_tc(
    const float* __restrict__ A,
    const float* __restrict__ B0, const float* __restrict__ B1,
    float* __restrict__ C0, float* __restrict__ C1, int M,
    const float* __restrict__ p0, const float* __restrict__ p1,
    const float* __restrict__ p2, int doRound)
{
    constexpr int NN = TPH * 128;
    extern __shared__ float smbuf[];

    const int tid = threadIdx.x;
    const int warp = tid >> 5;
    const int lane = tid & 31;
    const int wm = warp & 1, wn = warp >> 1;
    const int row0 = blockIdx.y * 128;

    int bx = blockIdx.x;
    bool isFeatHalf = (bx < TPH);
    const float* B = B0;
    float* C = C0;
    if (!isFeatHalf) { bx -= TPH; B = B1; C = C1; }
    const int col0 = bx * 128;

    wmma::fragment<wmma::accumulator, 16, 16, 8, float> acc[4][2];
    #pragma unroll
    for (int i = 0; i < 4; i++)
        #pragma unroll
        for (int j = 0; j < 2; j++)
            wmma::fill_fragment(acc[i][j], 0.0f);

    constexpr int KT = K >> 4;   // BK=16

    auto stage = [&](int buf, int k0) {
        float* As = smbuf + buf * ASTRIDE;
        float* Bs = smbuf + BBASE + buf * BSTRIDE;
        #pragma unroll
        for (int p = 0; p < 2; p++) {      // A: 128x16 = 512 float4
            int c = tid + p * 256;
            int r = c >> 2, q = c & 3;
            int gm = row0 + r;
            const float* srcp = A + (size_t)gm * K + k0 + q * 4;
            uint32_t d = (uint32_t)__cvta_generic_to_shared(&As[r * 20 + q * 4]);
            cp16(d, srcp, gm < M);
        }
        #pragma unroll
        for (int p = 0; p < 2; p++) {      // B: 16x128 = 512 float4
            int c = tid + p * 256;
            int r = c >> 5, nq = c & 31;
            const float* srcp = B + (size_t)(k0 + r) * NN + col0 + nq * 4;
            uint32_t d = (uint32_t)__cvta_generic_to_shared(&Bs[r * 132 + nq * 4]);
            cp16(d, srcp, true);
        }
        asm volatile("cp.async.commit_group;");
    };

    stage(0, 0);
    stage(1, 16);
    stage(2, 32);

    for (int kt = 0; kt < KT; kt++) {
        if (kt + 3 < KT) asm volatile("cp.async.wait_group 2;");
        else             asm volatile("cp.async.wait_group 0;");
        __syncthreads();

        int buf = kt & 3;
        const float* As = smbuf + buf * ASTRIDE;
        const float* Bs = smbuf + BBASE + buf * BSTRIDE;
        #pragma unroll
        for (int kk = 0; kk < 2; kk++) {
            wmma::fragment<wmma::matrix_a, 16, 16, 8, wmma::precision::tf32, wmma::row_major> a[4];
            wmma::fragment<wmma::matrix_b, 16, 16, 8, wmma::precision::tf32, wmma::row_major> b[2];
            #pragma unroll
            for (int i = 0; i < 4; i++)
                wmma::load_matrix_sync(a[i], As + (wm * 64 + i * 16) * 20 + kk * 8, 20);
            #pragma unroll
            for (int j = 0; j < 2; j++)
                wmma::load_matrix_sync(b[j], Bs + (kk * 8) * 132 + wn * 32 + j * 16, 132);
            #pragma unroll
            for (int i = 0; i < 4; i++)
                #pragma unroll
                for (int j = 0; j < 2; j++)
                    wmma::mma_sync(acc[i][j], a[i], b[j], acc[i][j]);
        }

        if (kt + 3 < KT) stage((kt + 3) & 3, (kt + 3) << 4);
    }

    if (MODE == 0) {
        #pragma unroll
        for (int i = 0; i < 4; i++)
            #pragma unroll
            for (int j = 0; j < 2; j++)
                wmma::store_matrix_sync(
                    C + (size_t)(row0 + wm * 64 + i * 16) * NN + col0 + wn * 32 + j * 16,
                    acc[i][j], NN, wmma::mem_row_major);

        // fused attention-coefficient epilogue (feat half only; head h == bx)
        if (isFeatHalf && p0 != nullptr) {
            float* sC = smbuf;   // 64 x 132
            float4 alv = *(const float4*)(p0 + col0 + lane * 4);
            float4 arv = *(const float4*)(p1 + col0 + lane * 4);
            __syncthreads();
            #pragma unroll
            for (int p = 0; p < 2; p++) {
                if (wm == p) {
                    #pragma unroll
                    for (int i = 0; i < 4; i++)
                        #pragma unroll
                        for (int j = 0; j < 2; j++)
                            wmma::store_matrix_sync(
                                sC + (size_t)(i * 16) * 132 + wn * 32 + j * 16,
                                acc[i][j], 132, wmma::mem_row_major);
                }
                __syncthreads();
                #pragma unroll
                for (int rr = 0; rr < 8; rr++) {
                    int lr = warp * 8 + rr;
                    int gm = row0 + p * 64 + lr;
                    float4 v = *(const float4*)(sC + (size_t)lr * 132 + lane * 4);
                    float sl = v.x * alv.x + v.y * alv.y + v.z * alv.z + v.w * alv.w;
                    float sr = v.x * arv.x + v.y * arv.y + v.z * arv.z + v.w * arv.w;
                    #pragma unroll
                    for (int o = 16; o; o >>= 1) {
                        sl += __shfl_xor_sync(0xffffffffu, sl, o);
                        sr += __shfl_xor_sync(0xffffffffu, sr, o);
                    }
                    if (lane == 0 && gm < M) {
                        g_el[gm * Hh + bx] = sl;
                        g_er[gm * Hh + bx] = sr;
                    }
                }
                __syncthreads();
            }
        }
    } else {
        // fused bias + layernorm epilogue: two 64-row phases through smem
        float* sC = smbuf;
        float4 bnv = ((const float4*)p0)[lane];
        float4 ggv = ((const float4*)p1)[lane];
        float4 bbv = ((const float4*)p2)[lane];
        #pragma unroll
        for (int p = 0; p < 2; p++) {
            if (wm == p) {
                #pragma unroll
                for (int i = 0; i < 4; i++)
                    #pragma unroll
                    for (int j = 0; j < 2; j++)
                        wmma::store_matrix_sync(
                            sC + (size_t)(i * 16) * 132 + wn * 32 + j * 16,
                            acc[i][j], 132, wmma::mem_row_major);
            }
            __syncthreads();
            #pragma unroll
            for (int rr = 0; rr < 8; rr++) {
                int lr = warp * 8 + rr;
                int gm = row0 + p * 64 + lr;
                float4 v = *(const float4*)(sC + (size_t)lr * 132 + lane * 4);
                v.x += bnv.x; v.y += bnv.y; v.z += bnv.z; v.w += bnv.w;
                float s = v.x + v.y + v.z + v.w;
                #pragma unroll
                for (int o = 16; o; o >>= 1) s += __shfl_xor_sync(0xffffffffu, s, o);
                float mu = s * (1.f / 128.f);
                float dx = v.x - mu, dy = v.y - mu, dz = v.z - mu, dw = v.w - mu;
                float q = dx * dx + dy * dy + dz * dz + dw * dw;
                #pragma unroll
                for (int o = 16; o; o >>= 1) q += __shfl_xor_sync(0xffffffffu, q, o);
                float rstd = rsqrtf(q * (1.f / 128.f) + 1e-5f);
                float4 o4;
                o4.x = dx * rstd * ggv.x + bbv.x;
                o4.y = dy * rstd * ggv.y + bbv.y;
                o4.z = dz * rstd * ggv.z + bbv.z;
                o4.w = dw * rstd * ggv.w + bbv.w;
                if (doRound) {
                    o4.x = tf32r(o4.x); o4.y = tf32r(o4.y);
                    o4.z = tf32r(o4.z); o4.w = tf32r(o4.w);
                }
                if (gm < M)
                    *(float4*)(C + (size_t)gm * NN + lane * 4) = o4;
            }
            __syncthreads();
        }
    }
}

// ------- fused aggregation: per-warp (m,z) prologue + weighted accumulate ---------
// one warp per (node, head); no extra kernel, no g_m4/g_iz4 round trip
__global__ __launch_bounds__(128) void k_agg(const float* __restrict__ bgat) {
    int n = blockIdx.x;
    int h = threadIdx.x >> 5, lane = threadIdx.x & 31;
    int beg = g_rowptr[n], end = g_rowptr[n + 1];
    float ern = g_er[n * 4 + h];

    // phase 1: softmax max & denominator (lane-strided, warp-combined)
    float m = -1e30f, z = 0.f;
    for (int e = beg + lane; e < end; e += 32) {
        int s = g_csrsrc[e];
        float v = g_el[s * 4 + h] + ern;
        v = v > 0.f ? v : 0.2f * v;
        float M = fmaxf(m, v);
        z = z * __expf(m - M) + __expf(v - M);
        m = M;
    }
    #pragma unroll
    for (int o = 16; o; o >>= 1) {
        float mo = __shfl_xor_sync(0xffffffffu, m, o);
        float zo = __shfl_xor_sync(0xffffffffu, z, o);
        float M = fmaxf(m, mo);
        z = z * __expf(m - M) + zo * __expf(mo - M);
        m = M;
    }
    float iz = 1.f / fmaxf(z, 1e-20f);

    // phase 2: weighted accumulate (m, iz now warp-uniform constants)
    float4 acc = make_float4(0.f, 0.f, 0.f, 0.f);
    int e = beg;
    for (; e + 4 <= end; e += 4) {
        int s0 = g_csrsrc[e + 0];
        int s1 = g_csrsrc[e + 1];
        int s2 = g_csrsrc[e + 2];
        int s3 = g_csrsrc[e + 3];
        float v0 = g_el[s0 * 4 + h] + ern;
        float v1 = g_el[s1 * 4 + h] + ern;
        float v2 = g_el[s2 * 4 + h] + ern;
        float v3 = g_el[s3 * 4 + h] + ern;
        float4 f0 = *(const float4*)(g_feat + (size_t)s0 * HDd + h * Dd + lane * 4);
        float4 f1 = *(const float4*)(g_feat + (size_t)s1 * HDd + h * Dd + lane * 4);
        float4 f2 = *(const float4*)(g_feat + (size_t)s2 * HDd + h * Dd + lane * 4);
        float4 f3 = *(const float4*)(g_feat + (size_t)s3 * HDd + h * Dd + lane * 4);
        v0 = v0 > 0.f ? v0 : 0.2f * v0;
        v1 = v1 > 0.f ? v1 : 0.2f * v1;
        v2 = v2 > 0.f ? v2 : 0.2f * v2;
        v3 = v3 > 0.f ? v3 : 0.2f * v3;
        float w0 = __expf(v0 - m), w1 = __expf(v1 - m);
        float w2 = __expf(v2 - m), w3 = __expf(v3 - m);
        acc.x += w0 * f0.x + w1 * f1.x + w2 * f2.x + w3 * f3.x;
        acc.y += w0 * f0.y + w1 * f1.y + w2 * f2.y + w3 * f3.y;
        acc.z += w0 * f0.z + w1 * f1.z + w2 * f2.z + w3 * f3.z;
        acc.w += w0 * f0.w + w1 * f1.w + w2 * f2.w + w3 * f3.w;
    }
    for (; e < end; e++) {
        int s = g_csrsrc[e];
        float v = g_el[s * 4 + h] + ern;
        v = v > 0.f ? v : 0.2f * v;
        float w = __expf(v - m);
        float4 f = *(const float4*)(g_feat + (size_t)s * HDd + h * Dd + lane * 4);
        acc.x += w * f.x; acc.y += w * f.y; acc.z += w * f.z; acc.w += w * f.w;
    }

    float* rp = g_res + (size_t)n * HDd + h * Dd + lane * 4;
    float4 r = *(float4*)rp;
    float4 bg = *(const float4*)(bgat + h * Dd + lane * 4);
    float4 o;
    o.x = acc.x * iz + r.x + bg.x;
    o.y = acc.y * iz + r.y + bg.y;
    o.z = acc.z * iz + r.z + bg.z;
    o.w = acc.w * iz + r.w + bg.w;
    o.x = o.x > 0.f ? o.x : 0.01f * o.x;
    o.y = o.y > 0.f ? o.y : 0.01f * o.y;
    o.z = o.z > 0.f ? o.z : 0.01f * o.z;
    o.w = o.w > 0.f ? o.w : 0.01f * o.w;
    o.x = tf32r(o.x); o.y = tf32r(o.y); o.z = tf32r(o.z); o.w = tf32r(o.w);
    *(float4*)rp = o;
}

// ---------------- launch ----------------
extern "C" void kernel_launch(void* const* d_in, const int* in_sizes, int n_in,
                              void* d_out, int out_size)
{
    const float* features = (const float*)d_in[0];
    const int*   src      = (const int*)  d_in[1];
    const int*   dst      = (const int*)  d_in[2];
    const float* W_fc     = (const float*)d_in[3];
    const float* attn_l   = (const float*)d_in[4];
    const float* attn_r   = (const float*)d_in[5];
    const float* W_res    = (const float*)d_in[6];
    const float* b_gat    = (const float*)d_in[7];
    const float* W_nrm    = (const float*)d_in[8];
    const float* b_nrm    = (const float*)d_in[9];
    const float* ln_g     = (const float*)d_in[10];
    const float* ln_b     = (const float*)d_in[11];
    float* out = (float*)d_out;

    float *feat, *res, *xA, *xB, *x0, *wr;
    cudaGetSymbolAddress((void**)&feat, g_feat);
    cudaGetSymbolAddress((void**)&res,  g_res);
    cudaGetSymbolAddress((void**)&xA,   g_xA);
    cudaGetSymbolAddress((void**)&xB,   g_xB);
    cudaGetSymbolAddress((void**)&x0,   g_x0);
    cudaGetSymbolAddress((void**)&wr,   g_wr);

    static int smemSet = 0;
    if (!smemSet) {
        cudaFuncSetAttribute(gemm_tc<Dd, HDd / 128, 0>,
                             cudaFuncAttributeMaxDynamicSharedMemorySize, SMBYTES);
        cudaFuncSetAttribute(gemm_tc<HDd, 1, 1>,
                             cudaFuncAttributeMaxDynamicSharedMemorySize, SMBYTES);
        smemSet = 1;
    }

    // preamble (rounding + zero), count, scan -> dual GEMM is launch #4 for ncu
    k_pre<<<(NFEAT + 255) / 256, 256>>>(W_fc, W_res, W_nrm, features);
    k_count<<<(Ee + 255) / 256, 256>>>(dst);
    k_scan<<<1, 1024>>>();

    const int gy = (Nn + 127) / 128;   // 391

    const float* xin = x0;
    for (int l = 0; l < Ll; l++) {
        const float* Wf = wr + (size_t)l * WSZ;
        const float* Wr = wr + (size_t)(Ll + l) * WSZ;
        const float* Wn = wr + (size_t)(2 * Ll + l) * WSZ;

        // fused: feat = xin@Wf (+ el/er in epilogue) ; res = xin@Wr
        dim3 g1(2 * (HDd / 128), gy);
        gemm_tc<Dd, HDd / 128, 0><<<g1, 256, SMBYTES>>>(
            xin, Wf, Wr, feat, res, Nn,
            attn_l + l * Hh * Dd, attn_r + l * Hh * Dd, nullptr, 0);

        if (l == 0) k_fill<<<(Ee + 255) / 256, 256>>>(src, dst);

        k_agg<<<Nn, 128>>>(b_gat + l * HDd);

        // xout = layernorm(res @ Wn + b_nrm), fused LN epilogue
        float* xout = (l == Ll - 1) ? out : ((l & 1) ? xB : xA);
        dim3 g2(1, gy);
        gemm_tc<HDd, 1, 1><<<g2, 256, SMBYTES>>>(
            res, Wn, nullptr, xout, nullptr, Nn,
            b_nrm + l * Dd, ln_g + l * Dd, ln_b + l * Dd, l != Ll - 1);
        xin = xout;
    }
}

// round 9
// speedup vs baseline: 1.2038x; 1.0619x over previous
#include <cuda_runtime.h>
#include <cuda_fp16.h>
#include <mma.h>
#include <cstdint>
using namespace nvcuda;

#define Nn 50000
#define Ee 800000
#define Hh 4
#define Dd 128
#define HDd 512
#define Ll 4
#define MPAD 50048   // 391 * 128, pads GEMM M-tiles so epilogue stores are unguarded

#define WSZ (Dd * HDd)          // 65536 per weight matrix
#define NWEIGHT (3 * Ll * WSZ)  // 786432
#define NFEAT (Nn * Dd)         // 6.4M

// dynamic smem (floats): 4 A bufs (128x20) + 4 B bufs (16x132)
#define ASTRIDE 2560            // 128*20
#define BBASE   10240           // 4*ASTRIDE
#define BSTRIDE 2112            // 16*132
#define SMPOOL  18688           // floats
#define SMBYTES (SMPOOL * 4)    // 74752 bytes

// ---------------- scratch (static device memory; no allocations) ----------------
__device__ __align__(16) __half g_featH[(size_t)Nn * HDd];  // fp16 feat (k_agg payload)
__device__ __align__(16) float g_res [(size_t)MPAD * HDd];
__device__ __align__(16) float g_el[Nn * Hh];
__device__ __align__(16) float g_er[Nn * Hh];
__device__ __align__(16) float g_xA[(size_t)Nn * Dd];
__device__ __align__(16) float g_xB[(size_t)Nn * Dd];
__device__ __align__(16) float g_x0[(size_t)Nn * Dd];     // tf32-rounded features
__device__ __align__(16) float g_wr[NWEIGHT];             // tf32-rounded weights
__device__ int g_deg[Nn];
__device__ int g_rowptr[Nn + 1];
__device__ int g_cursor[Nn];
__device__ int g_csrsrc[Ee];

__device__ __forceinline__ float tf32r(float x) { return wmma::__float_to_tf32(x); }

// ---------------- preamble: round weights+features to tf32, zero deg ----------------
__global__ void k_pre(const float* __restrict__ Wf, const float* __restrict__ Wr,
                      const float* __restrict__ Wn, const float* __restrict__ feats)
{
    int i = blockIdx.x * blockDim.x + threadIdx.x;
    if (i < NFEAT) g_x0[i] = tf32r(feats[i]);
    if (i < Ll * WSZ) {
        g_wr[i]                = tf32r(Wf[i]);
        g_wr[Ll * WSZ + i]     = tf32r(Wr[i]);
        g_wr[2 * Ll * WSZ + i] = tf32r(Wn[i]);
    }
    if (i < Nn) g_deg[i] = 0;
}

__global__ void k_count(const int* __restrict__ dst) {
    int i = blockIdx.x * blockDim.x + threadIdx.x;
    if (i < Ee) atomicAdd(&g_deg[dst[i]], 1);
}

// single-block exclusive scan over g_deg -> g_rowptr (+ cursor init fused)
__global__ void k_scan() {
    __shared__ int sh[1024];
    __shared__ int carry;
    int t = threadIdx.x;
    if (t == 0) { carry = 0; g_rowptr[0] = 0; }
    __syncthreads();
    for (int base = 0; base < Nn; base += 1024) {
        int i = base + t;
        int v = (i < Nn) ? g_deg[i] : 0;
        sh[t] = v;
        __syncthreads();
        #pragma unroll
        for (int off = 1; off < 1024; off <<= 1) {
            int tv = (t >= off) ? sh[t - off] : 0;
            __syncthreads();
            sh[t] += tv;
            __syncthreads();
        }
        int incl = sh[t];
        int c = carry;
        __syncthreads();
        if (i < Nn) {
            g_rowptr[i + 1] = c + incl;
            g_cursor[i] = c + incl - v;
        }
        if (t == 1023) carry = c + incl;
        __syncthreads();
    }
}

__global__ void k_fill(const int* __restrict__ src, const int* __restrict__ dst) {
    int i = blockIdx.x * blockDim.x + threadIdx.x;
    if (i < Ee) {
        int p = atomicAdd(&g_cursor[dst[i]], 1);
        g_csrsrc[p] = src[i];
    }
}

// ---------------- cp.async helper ----------------
__device__ __forceinline__ void cp16(uint32_t dst, const void* src, bool pred) {
    int sz = pred ? 16 : 0;
    asm volatile("cp.async.cg.shared.global [%0], [%1], 16, %2;\n"
                 :: "r"(dst), "l"(src), "r"(sz));
}

// ---------------- tf32 tensor-core GEMM, BK=16, 4-stage ring ----------------------
// MODE 0: dual-output. res half: plain fp32 store (padded C).
//         feat half (bx < TPH, p0/p1 = attn_l/attn_r): NO fp32 store; epilogue
//         computes el/er AND stores feat as fp16 to g_featH (guarded rows).
// MODE 1: TPH==1, fused bias+layernorm epilogue, guarded stores
template<int K, int TPH, int MODE>
__global__ __launch_bounds__(256) void gemm_tc(
    const float* __restrict__ A,
    const float* __restrict__ B0, const float* __restrict__ B1,
    float* __restrict__ C0, float* __restrict__ C1, int M,
    const float* __restrict__ p0, const float* __restrict__ p1,
    const float* __restrict__ p2, int doRound)
{
    constexpr int NN = TPH * 128;
    extern __shared__ float smbuf[];

    const int tid = threadIdx.x;
    const int warp = tid >> 5;
    const int lane = tid & 31;
    const int wm = warp & 1, wn = warp >> 1;
    const int row0 = blockIdx.y * 128;

    int bx = blockIdx.x;
    bool isFeatHalf = (bx < TPH);
    const float* B = B0;
    float* C = C0;
    if (!isFeatHalf) { bx -= TPH; B = B1; C = C1; }
    const int col0 = bx * 128;

    wmma::fragment<wmma::accumulator, 16, 16, 8, float> acc[4][2];
    #pragma unroll
    for (int i = 0; i < 4; i++)
        #pragma unroll
        for (int j = 0; j < 2; j++)
            wmma::fill_fragment(acc[i][j], 0.0f);

    constexpr int KT = K >> 4;   // BK=16

    auto stage = [&](int buf, int k0) {
        float* As = smbuf + buf * ASTRIDE;
        float* Bs = smbuf + BBASE + buf * BSTRIDE;
        #pragma unroll
        for (int p = 0; p < 2; p++) {      // A: 128x16 = 512 float4
            int c = tid + p * 256;
            int r = c >> 2, q = c & 3;
            int gm = row0 + r;
            const float* srcp = A + (size_t)gm * K + k0 + q * 4;
            uint32_t d = (uint32_t)__cvta_generic_to_shared(&As[r * 20 + q * 4]);
            cp16(d, srcp, gm < M);
        }
        #pragma unroll
        for (int p = 0; p < 2; p++) {      // B: 16x128 = 512 float4
            int c = tid + p * 256;
            int r = c >> 5, nq = c & 31;
            const float* srcp = B + (size_t)(k0 + r) * NN + col0 + nq * 4;
            uint32_t d = (uint32_t)__cvta_generic_to_shared(&Bs[r * 132 + nq * 4]);
            cp16(d, srcp, true);
        }
        asm volatile("cp.async.commit_group;");
    };

    stage(0, 0);
    stage(1, 16);
    stage(2, 32);

    for (int kt = 0; kt < KT; kt++) {
        if (kt + 3 < KT) asm volatile("cp.async.wait_group 2;");
        else             asm volatile("cp.async.wait_group 0;");
        __syncthreads();

        int buf = kt & 3;
        const float* As = smbuf + buf * ASTRIDE;
        const float* Bs = smbuf + BBASE + buf * BSTRIDE;
        #pragma unroll
        for (int kk = 0; kk < 2; kk++) {
            wmma::fragment<wmma::matrix_a, 16, 16, 8, wmma::precision::tf32, wmma::row_major> a[4];
            wmma::fragment<wmma::matrix_b, 16, 16, 8, wmma::precision::tf32, wmma::row_major> b[2];
            #pragma unroll
            for (int i = 0; i < 4; i++)
                wmma::load_matrix_sync(a[i], As + (wm * 64 + i * 16) * 20 + kk * 8, 20);
            #pragma unroll
            for (int j = 0; j < 2; j++)
                wmma::load_matrix_sync(b[j], Bs + (kk * 8) * 132 + wn * 32 + j * 16, 132);
            #pragma unroll
            for (int i = 0; i < 4; i++)
                #pragma unroll
                for (int j = 0; j < 2; j++)
                    wmma::mma_sync(acc[i][j], a[i], b[j], acc[i][j]);
        }

        if (kt + 3 < KT) stage((kt + 3) & 3, (kt + 3) << 4);
    }

    if (MODE == 0) {
        if (!isFeatHalf) {
            // res half: plain fp32 store to padded C
            #pragma unroll
            for (int i = 0; i < 4; i++)
                #pragma unroll
                for (int j = 0; j < 2; j++)
                    wmma::store_matrix_sync(
                        C + (size_t)(row0 + wm * 64 + i * 16) * NN + col0 + wn * 32 + j * 16,
                        acc[i][j], NN, wmma::mem_row_major);
        } else {
            // feat half: attn coefficients + fp16 feat store (head h == bx)
            float* sC = smbuf;   // 64 x 132
            float4 alv = *(const float4*)(p0 + col0 + lane * 4);
            float4 arv = *(const float4*)(p1 + col0 + lane * 4);
            __syncthreads();
            #pragma unroll
            for (int p = 0; p < 2; p++) {
                if (wm == p) {
                    #pragma unroll
                    for (int i = 0; i < 4; i++)
                        #pragma unroll
                        for (int j = 0; j < 2; j++)
                            wmma::store_matrix_sync(
                                sC + (size_t)(i * 16) * 132 + wn * 32 + j * 16,
                                acc[i][j], 132, wmma::mem_row_major);
                }
                __syncthreads();
                #pragma unroll
                for (int rr = 0; rr < 8; rr++) {
                    int lr = warp * 8 + rr;
                    int gm = row0 + p * 64 + lr;
                    float4 v = *(const float4*)(sC + (size_t)lr * 132 + lane * 4);
                    bool valid = gm < M;
                    if (valid) {
                        __half2 h0 = __floats2half2_rn(v.x, v.y);
                        __half2 h1 = __floats2half2_rn(v.z, v.w);
                        uint2 u;
                        u.x = *reinterpret_cast<unsigned*>(&h0);
                        u.y = *reinterpret_cast<unsigned*>(&h1);
                        *(uint2*)(g_featH + (size_t)gm * HDd + col0 + lane * 4) = u;
                    }
                    float sl = v.x * alv.x + v.y * alv.y + v.z * alv.z + v.w * alv.w;
                    float sr = v.x * arv.x + v.y * arv.y + v.z * arv.z + v.w * arv.w;
                    #pragma unroll
                    for (int o = 16; o; o >>= 1) {
                        sl += __shfl_xor_sync(0xffffffffu, sl, o);
                        sr += __shfl_xor_sync(0xffffffffu, sr, o);
                    }
                    if (lane == 0 && valid) {
                        g_el[gm * Hh + bx] = sl;
                        g_er[gm * Hh + bx] = sr;
                    }
                }
                __syncthreads();
            }
        }
    } else {
        // fused bias + layernorm epilogue: two 64-row phases through smem
        float* sC = smbuf;
        float4 bnv = ((const float4*)p0)[lane];
        float4 ggv = ((const float4*)p1)[lane];
        float4 bbv = ((const float4*)p2)[lane];
        #pragma unroll
        for (int p = 0; p < 2; p++) {
            if (wm == p) {
                #pragma unroll
                for (int i = 0; i < 4; i++)
                    #pragma unroll
                    for (int j = 0; j < 2; j++)
                        wmma::store_matrix_sync(
                            sC + (size_t)(i * 16) * 132 + wn * 32 + j * 16,
                            acc[i][j], 132, wmma::mem_row_major);
            }
            __syncthreads();
            #pragma unroll
            for (int rr = 0; rr < 8; rr++) {
                int lr = warp * 8 + rr;
                int gm = row0 + p * 64 + lr;
                float4 v = *(const float4*)(sC + (size_t)lr * 132 + lane * 4);
                v.x += bnv.x; v.y += bnv.y; v.z += bnv.z; v.w += bnv.w;
                float s = v.x + v.y + v.z + v.w;
                #pragma unroll
                for (int o = 16; o; o >>= 1) s += __shfl_xor_sync(0xffffffffu, s, o);
                float mu = s * (1.f / 128.f);
                float dx = v.x - mu, dy = v.y - mu, dz = v.z - mu, dw = v.w - mu;
                float q = dx * dx + dy * dy + dz * dz + dw * dw;
                #pragma unroll
                for (int o = 16; o; o >>= 1) q += __shfl_xor_sync(0xffffffffu, q, o);
                float rstd = rsqrtf(q * (1.f / 128.f) + 1e-5f);
                float4 o4;
                o4.x = dx * rstd * ggv.x + bbv.x;
                o4.y = dy * rstd * ggv.y + bbv.y;
                o4.z = dz * rstd * ggv.z + bbv.z;
                o4.w = dw * rstd * ggv.w + bbv.w;
                if (doRound) {
                    o4.x = tf32r(o4.x); o4.y = tf32r(o4.y);
                    o4.z = tf32r(o4.z); o4.w = tf32r(o4.w);
                }
                if (gm < M)
                    *(float4*)(C + (size_t)gm * NN + lane * 4) = o4;
            }
            __syncthreads();
        }
    }
}

// ------- fused aggregation: per-warp (m,z) prologue + weighted accumulate ---------
// one warp per (node, head); feat gathered as fp16 (half traffic)
__global__ __launch_bounds__(128) void k_agg(const float* __restrict__ bgat) {
    int n = blockIdx.x;
    int h = threadIdx.x >> 5, lane = threadIdx.x & 31;
    int beg = g_rowptr[n], end = g_rowptr[n + 1];
    float ern = g_er[n * 4 + h];

    // phase 1: softmax max & denominator (lane-strided, warp-combined)
    float m = -1e30f, z = 0.f;
    for (int e = beg + lane; e < end; e += 32) {
        int s = g_csrsrc[e];
        float v = g_el[s * 4 + h] + ern;
        v = v > 0.f ? v : 0.2f * v;
        float M = fmaxf(m, v);
        z = z * __expf(m - M) + __expf(v - M);
        m = M;
    }
    #pragma unroll
    for (int o = 16; o; o >>= 1) {
        float mo = __shfl_xor_sync(0xffffffffu, m, o);
        float zo = __shfl_xor_sync(0xffffffffu, z, o);
        float M = fmaxf(m, mo);
        z = z * __expf(m - M) + zo * __expf(mo - M);
        m = M;
    }
    float iz = 1.f / fmaxf(z, 1e-20f);

    // phase 2: weighted accumulate (m, iz warp-uniform constants)
    const __half* fbase = g_featH + h * Dd + lane * 4;
    float4 acc = make_float4(0.f, 0.f, 0.f, 0.f);
    int e = beg;
    for (; e + 4 <= end; e += 4) {
        int s0 = g_csrsrc[e + 0];
        int s1 = g_csrsrc[e + 1];
        int s2 = g_csrsrc[e + 2];
        int s3 = g_csrsrc[e + 3];
        float v0 = g_el[s0 * 4 + h] + ern;
        float v1 = g_el[s1 * 4 + h] + ern;
        float v2 = g_el[s2 * 4 + h] + ern;
        float v3 = g_el[s3 * 4 + h] + ern;
        uint2 u0 = *(const uint2*)(fbase + (size_t)s0 * HDd);
        uint2 u1 = *(const uint2*)(fbase + (size_t)s1 * HDd);
        uint2 u2 = *(const uint2*)(fbase + (size_t)s2 * HDd);
        uint2 u3 = *(const uint2*)(fbase + (size_t)s3 * HDd);
        v0 = v0 > 0.f ? v0 : 0.2f * v0;
        v1 = v1 > 0.f ? v1 : 0.2f * v1;
        v2 = v2 > 0.f ? v2 : 0.2f * v2;
        v3 = v3 > 0.f ? v3 : 0.2f * v3;
        float w0 = __expf(v0 - m), w1 = __expf(v1 - m);
        float w2 = __expf(v2 - m), w3 = __expf(v3 - m);
        float2 a0 = __half22float2(*(__half2*)&u0.x), b0 = __half22float2(*(__half2*)&u0.y);
        float2 a1 = __half22float2(*(__half2*)&u1.x), b1 = __half22float2(*(__half2*)&u1.y);
        float2 a2 = __half22float2(*(__half2*)&u2.x), b2 = __half22float2(*(__half2*)&u2.y);
        float2 a3 = __half22float2(*(__half2*)&u3.x), b3 = __half22float2(*(__half2*)&u3.y);
        acc.x += w0 * a0.x + w1 * a1.x + w2 * a2.x + w3 * a3.x;
        acc.y += w0 * a0.y + w1 * a1.y + w2 * a2.y + w3 * a3.y;
        acc.z += w0 * b0.x + w1 * b1.x + w2 * b2.x + w3 * b3.x;
        acc.w += w0 * b0.y + w1 * b1.y + w2 * b2.y + w3 * b3.y;
    }
    for (; e < end; e++) {
        int s = g_csrsrc[e];
        float v = g_el[s * 4 + h] + ern;
        v = v > 0.f ? v : 0.2f * v;
        float w = __expf(v - m);
        uint2 u = *(const uint2*)(fbase + (size_t)s * HDd);
        float2 a = __half22float2(*(__half2*)&u.x), b = __half22float2(*(__half2*)&u.y);
        acc.x += w * a.x; acc.y += w * a.y; acc.z += w * b.x; acc.w += w * b.y;
    }

    float* rp = g_res + (size_t)n * HDd + h * Dd + lane * 4;
    float4 r = *(float4*)rp;
    float4 bg = *(const float4*)(bgat + h * Dd + lane * 4);
    float4 o;
    o.x = acc.x * iz + r.x + bg.x;
    o.y = acc.y * iz + r.y + bg.y;
    o.z = acc.z * iz + r.z + bg.z;
    o.w = acc.w * iz + r.w + bg.w;
    o.x = o.x > 0.f ? o.x : 0.01f * o.x;
    o.y = o.y > 0.f ? o.y : 0.01f * o.y;
    o.z = o.z > 0.f ? o.z : 0.01f * o.z;
    o.w = o.w > 0.f ? o.w : 0.01f * o.w;
    o.x = tf32r(o.x); o.y = tf32r(o.y); o.z = tf32r(o.z); o.w = tf32r(o.w);
    *(float4*)rp = o;
}

// ---------------- launch ----------------
extern "C" void kernel_launch(void* const* d_in, const int* in_sizes, int n_in,
                              void* d_out, int out_size)
{
    const float* features = (const float*)d_in[0];
    const int*   src      = (const int*)  d_in[1];
    const int*   dst      = (const int*)  d_in[2];
    const float* W_fc     = (const float*)d_in[3];
    const float* attn_l   = (const float*)d_in[4];
    const float* attn_r   = (const float*)d_in[5];
    const float* W_res    = (const float*)d_in[6];
    const float* b_gat    = (const float*)d_in[7];
    const float* W_nrm    = (const float*)d_in[8];
    const float* b_nrm    = (const float*)d_in[9];
    const float* ln_g     = (const float*)d_in[10];
    const float* ln_b     = (const float*)d_in[11];
    float* out = (float*)d_out;

    float *res, *xA, *xB, *x0, *wr;
    cudaGetSymbolAddress((void**)&res,  g_res);
    cudaGetSymbolAddress((void**)&xA,   g_xA);
    cudaGetSymbolAddress((void**)&xB,   g_xB);
    cudaGetSymbolAddress((void**)&x0,   g_x0);
    cudaGetSymbolAddress((void**)&wr,   g_wr);

    static int smemSet = 0;
    if (!smemSet) {
        cudaFuncSetAttribute(gemm_tc<Dd, HDd / 128, 0>,
                             cudaFuncAttributeMaxDynamicSharedMemorySize, SMBYTES);
        cudaFuncSetAttribute(gemm_tc<HDd, 1, 1>,
                             cudaFuncAttributeMaxDynamicSharedMemorySize, SMBYTES);
        smemSet = 1;
    }

    // preamble (rounding + zero), count, scan -> dual GEMM is launch #4 for ncu
    k_pre<<<(NFEAT + 255) / 256, 256>>>(W_fc, W_res, W_nrm, features);
    k_count<<<(Ee + 255) / 256, 256>>>(dst);
    k_scan<<<1, 1024>>>();

    const int gy = (Nn + 127) / 128;   // 391

    const float* xin = x0;
    for (int l = 0; l < Ll; l++) {
        const float* Wf = wr + (size_t)l * WSZ;
        const float* Wr = wr + (size_t)(Ll + l) * WSZ;
        const float* Wn = wr + (size_t)(2 * Ll + l) * WSZ;

        // fused: featH(fp16) + el/er = xin@Wf ; res = xin@Wr
        dim3 g1(2 * (HDd / 128), gy);
        gemm_tc<Dd, HDd / 128, 0><<<g1, 256, SMBYTES>>>(
            xin, Wf, Wr, nullptr, res, Nn,
            attn_l + l * Hh * Dd, attn_r + l * Hh * Dd, nullptr, 0);

        if (l == 0) k_fill<<<(Ee + 255) / 256, 256>>>(src, dst);

        k_agg<<<Nn, 128>>>(b_gat + l * HDd);

        // xout = layernorm(res @ Wn + b_nrm), fused LN epilogue
        float* xout = (l == Ll - 1) ? out : ((l & 1) ? xB : xA);
        dim3 g2(1, gy);
        gemm_tc<HDd, 1, 1><<<g2, 256, SMBYTES>>>(
            res, Wn, nullptr, xout, nullptr, Nn,
            b_nrm + l * Dd, ln_g + l * Dd, ln_b + l * Dd, l != Ll - 1);
        xin = xout;
    }
}

// round 10
// speedup vs baseline: 1.2980x; 1.0783x over previous
#include <cuda_runtime.h>
#include <cuda_fp16.h>
#include <mma.h>
#include <cstdint>
using namespace nvcuda;

#define Nn 50000
#define Ee 800000
#define Hh 4
#define Dd 128
#define HDd 512
#define Ll 4
#define MPAD 50048   // 391*128, pads fp32 res buffer so GEMM1 res stores are unguarded

#define WSZ (Dd * HDd)          // 65536 per weight matrix
#define NWEIGHT (3 * Ll * WSZ)  // 786432
#define NFEAT (Nn * Dd)         // 6.4M

// static smem ring (halves): 4 A bufs (128 rows x 24 h) + 4 B bufs (16 rows x 136 h)
#define ASTRIDE_H 3072          // 128*24
#define BBASE_H   12288         // 4*ASTRIDE_H
#define BSTRIDE_H 2176          // 16*136
#define SMHALVES  20992         // 41984 bytes total; epilogue reuses as 64x132 floats

// ---------------- scratch (static device memory; no allocations) ----------------
__device__ __align__(16) __half g_featH[(size_t)Nn * HDd];  // fp16 feat (k_agg payload)
__device__ __align__(16) float  g_res  [(size_t)MPAD * HDd]; // fp32 x@Wr (k_agg residual in)
__device__ __align__(16) __half g_resH [(size_t)Nn * HDd];  // fp16 k_agg out (GEMM2 A)
__device__ __align__(16) float  g_el[Nn * Hh];
__device__ __align__(16) float  g_er[Nn * Hh];
__device__ __align__(16) __half g_xh0[(size_t)Nn * Dd];     // fp16 features
__device__ __align__(16) __half g_xhA[(size_t)Nn * Dd];
__device__ __align__(16) __half g_xhB[(size_t)Nn * Dd];
__device__ __align__(16) __half g_wh[NWEIGHT];              // fp16 weights
__device__ int g_deg[Nn];
__device__ int g_rowptr[Nn + 1];
__device__ int g_cursor[Nn];
__device__ int g_csrsrc[Ee];

// ---------------- preamble: convert weights+features to fp16, zero deg -------------
__global__ void k_pre(const float* __restrict__ Wf, const float* __restrict__ Wr,
                      const float* __restrict__ Wn, const float* __restrict__ feats)
{
    int i = blockIdx.x * blockDim.x + threadIdx.x;
    if (i < NFEAT) g_xh0[i] = __float2half_rn(feats[i]);
    if (i < Ll * WSZ) {
        g_wh[i]                = __float2half_rn(Wf[i]);
        g_wh[Ll * WSZ + i]     = __float2half_rn(Wr[i]);
        g_wh[2 * Ll * WSZ + i] = __float2half_rn(Wn[i]);
    }
    if (i < Nn) g_deg[i] = 0;
}

__global__ void k_count(const int* __restrict__ dst) {
    int i = blockIdx.x * blockDim.x + threadIdx.x;
    if (i < Ee) atomicAdd(&g_deg[dst[i]], 1);
}

// single-block exclusive scan over g_deg -> g_rowptr (+ cursor init fused)
__global__ void k_scan() {
    __shared__ int sh[1024];
    __shared__ int carry;
    int t = threadIdx.x;
    if (t == 0) { carry = 0; g_rowptr[0] = 0; }
    __syncthreads();
    for (int base = 0; base < Nn; base += 1024) {
        int i = base + t;
        int v = (i < Nn) ? g_deg[i] : 0;
        sh[t] = v;
        __syncthreads();
        #pragma unroll
        for (int off = 1; off < 1024; off <<= 1) {
            int tv = (t >= off) ? sh[t - off] : 0;
            __syncthreads();
            sh[t] += tv;
            __syncthreads();
        }
        int incl = sh[t];
        int c = carry;
        __syncthreads();
        if (i < Nn) {
            g_rowptr[i + 1] = c + incl;
            g_cursor[i] = c + incl - v;
        }
        if (t == 1023) carry = c + incl;
        __syncthreads();
    }
}

__global__ void k_fill(const int* __restrict__ src, const int* __restrict__ dst) {
    int i = blockIdx.x * blockDim.x + threadIdx.x;
    if (i < Ee) {
        int p = atomicAdd(&g_cursor[dst[i]], 1);
        g_csrsrc[p] = src[i];
    }
}

// ---------------- cp.async helper ----------------
__device__ __forceinline__ void cp16(uint32_t dst, const void* src, bool pred) {
    int sz = pred ? 16 : 0;
    asm volatile("cp.async.cg.shared.global [%0], [%1], 16, %2;\n"
                 :: "r"(dst), "l"(src), "r"(sz));
}

// ---------------- fp16 tensor-core GEMM (m16n16k16), BK=16, 4-stage ring ----------
// CTA 128x128, 8 warps (2m x 4n), warp tile 64x32, fp32 accumulate.
// MODE 0: dual-output. res half (bx>=TPH): fp32 store to padded C0.
//         feat half (bx<TPH): epilogue computes el/er (p0/p1) + fp16 feat store.
// MODE 1: TPH==1, fused bias+layernorm epilogue; doHalf -> half to CH else fp32 to C0.
template<int K, int TPH, int MODE>
__global__ __launch_bounds__(256) void gemm_h(
    const __half* __restrict__ A,
    const __half* __restrict__ B0, const __half* __restrict__ B1,
    float* __restrict__ C0, __half* __restrict__ CH, int M,
    const float* __restrict__ p0, const float* __restrict__ p1,
    const float* __restrict__ p2, int doHalf)
{
    constexpr int NN = TPH * 128;
    __shared__ __align__(16) __half smh[SMHALVES];
    float* smf = reinterpret_cast<float*>(smh);

    const int tid = threadIdx.x;
    const int warp = tid >> 5;
    const int lane = tid & 31;
    const int wm = warp & 1, wn = warp >> 1;
    const int row0 = blockIdx.y * 128;

    int bx = blockIdx.x;
    bool isFeatHalf = (bx < TPH);
    const __half* B = B0;
    if (!isFeatHalf) { bx -= TPH; B = B1; }
    const int col0 = bx * 128;

    wmma::fragment<wmma::accumulator, 16, 16, 16, float> acc[4][2];
    #pragma unroll
    for (int i = 0; i < 4; i++)
        #pragma unroll
        for (int j = 0; j < 2; j++)
            wmma::fill_fragment(acc[i][j], 0.0f);

    constexpr int KT = K >> 4;   // BK=16

    auto stage = [&](int buf, int k0) {
        __half* As = smh + buf * ASTRIDE_H;
        __half* Bs = smh + BBASE_H + buf * BSTRIDE_H;
        {   // A: 128 rows x 16 halves = 256 x 16B chunks (1/thread)
            int r = tid >> 1, q = tid & 1;
            int gm = row0 + r;
            const __half* srcp = A + (size_t)gm * K + k0 + q * 8;
            uint32_t d = (uint32_t)__cvta_generic_to_shared(&As[r * 24 + q * 8]);
            cp16(d, srcp, gm < M);
        }
        {   // B: 16 rows x 128 halves = 256 x 16B chunks (1/thread)
            int r = tid >> 4, q = tid & 15;
            const __half* srcp = B + (size_t)(k0 + r) * NN + col0 + q * 8;
            uint32_t d = (uint32_t)__cvta_generic_to_shared(&Bs[r * 136 + q * 8]);
            cp16(d, srcp, true);
        }
        asm volatile("cp.async.commit_group;");
    };

    stage(0, 0);
    stage(1, 16);
    stage(2, 32);

    for (int kt = 0; kt < KT; kt++) {
        if (kt + 3 < KT) asm volatile("cp.async.wait_group 2;");
        else             asm volatile("cp.async.wait_group 0;");
        __syncthreads();

        int buf = kt & 3;
        const __half* As = smh + buf * ASTRIDE_H;
        const __half* Bs = smh + BBASE_H + buf * BSTRIDE_H;
        wmma::fragment<wmma::matrix_a, 16, 16, 16, __half, wmma::row_major> a[4];
        wmma::fragment<wmma::matrix_b, 16, 16, 16, __half, wmma::row_major> b[2];
        #pragma unroll
        for (int i = 0; i < 4; i++)
            wmma::load_matrix_sync(a[i], As + (wm * 64 + i * 16) * 24, 24);
        #pragma unroll
        for (int j = 0; j < 2; j++)
            wmma::load_matrix_sync(b[j], Bs + wn * 32 + j * 16, 136);
        #pragma unroll
        for (int i = 0; i < 4; i++)
            #pragma unroll
            for (int j = 0; j < 2; j++)
                wmma::mma_sync(acc[i][j], a[i], b[j], acc[i][j]);

        if (kt + 3 < KT) stage((kt + 3) & 3, (kt + 3) << 4);
    }

    if (MODE == 0) {
        if (!isFeatHalf) {
            // res half: fp32 store to padded C0 (MPAD rows)
            #pragma unroll
            for (int i = 0; i < 4; i++)
                #pragma unroll
                for (int j = 0; j < 2; j++)
                    wmma::store_matrix_sync(
                        C0 + (size_t)(row0 + wm * 64 + i * 16) * NN + col0 + wn * 32 + j * 16,
                        acc[i][j], NN, wmma::mem_row_major);
        } else {
            // feat half: attn coefficients + fp16 feat store (head h == bx)
            float* sC = smf;   // 64 x 132 floats (33.8KB <= 41.98KB pool)
            float4 alv = *(const float4*)(p0 + col0 + lane * 4);
            float4 arv = *(const float4*)(p1 + col0 + lane * 4);
            __syncthreads();
            #pragma unroll
            for (int p = 0; p < 2; p++) {
                if (wm == p) {
                    #pragma unroll
                    for (int i = 0; i < 4; i++)
                        #pragma unroll
                        for (int j = 0; j < 2; j++)
                            wmma::store_matrix_sync(
                                sC + (size_t)(i * 16) * 132 + wn * 32 + j * 16,
                                acc[i][j], 132, wmma::mem_row_major);
                }
                __syncthreads();
                #pragma unroll
                for (int rr = 0; rr < 8; rr++) {
                    int lr = warp * 8 + rr;
                    int gm = row0 + p * 64 + lr;
                    float4 v = *(const float4*)(sC + (size_t)lr * 132 + lane * 4);
                    bool valid = gm < M;
                    if (valid) {
                        __half2 h0 = __floats2half2_rn(v.x, v.y);
                        __half2 h1 = __floats2half2_rn(v.z, v.w);
                        uint2 u;
                        u.x = *reinterpret_cast<unsigned*>(&h0);
                        u.y = *reinterpret_cast<unsigned*>(&h1);
                        *(uint2*)(g_featH + (size_t)gm * HDd + col0 + lane * 4) = u;
                    }
                    float sl = v.x * alv.x + v.y * alv.y + v.z * alv.z + v.w * alv.w;
                    float sr = v.x * arv.x + v.y * arv.y + v.z * arv.z + v.w * arv.w;
                    #pragma unroll
                    for (int o = 16; o; o >>= 1) {
                        sl += __shfl_xor_sync(0xffffffffu, sl, o);
                        sr += __shfl_xor_sync(0xffffffffu, sr, o);
                    }
                    if (lane == 0 && valid) {
                        g_el[gm * Hh + bx] = sl;
                        g_er[gm * Hh + bx] = sr;
                    }
                }
                __syncthreads();
            }
        }
    } else {
        // fused bias + layernorm epilogue: two 64-row phases through smem
        float* sC = smf;
        float4 bnv = ((const float4*)p0)[lane];
        float4 ggv = ((const float4*)p1)[lane];
        float4 bbv = ((const float4*)p2)[lane];
        #pragma unroll
        for (int p = 0; p < 2; p++) {
            __syncthreads();
            if (wm == p) {
                #pragma unroll
                for (int i = 0; i < 4; i++)
                    #pragma unroll
                    for (int j = 0; j < 2; j++)
                        wmma::store_matrix_sync(
                            sC + (size_t)(i * 16) * 132 + wn * 32 + j * 16,
                            acc[i][j], 132, wmma::mem_row_major);
            }
            __syncthreads();
            #pragma unroll
            for (int rr = 0; rr < 8; rr++) {
                int lr = warp * 8 + rr;
                int gm = row0 + p * 64 + lr;
                float4 v = *(const float4*)(sC + (size_t)lr * 132 + lane * 4);
                v.x += bnv.x; v.y += bnv.y; v.z += bnv.z; v.w += bnv.w;
                float s = v.x + v.y + v.z + v.w;
                #pragma unroll
                for (int o = 16; o; o >>= 1) s += __shfl_xor_sync(0xffffffffu, s, o);
                float mu = s * (1.f / 128.f);
                float dx = v.x - mu, dy = v.y - mu, dz = v.z - mu, dw = v.w - mu;
                float q = dx * dx + dy * dy + dz * dz + dw * dw;
                #pragma unroll
                for (int o = 16; o; o >>= 1) q += __shfl_xor_sync(0xffffffffu, q, o);
                float rstd = rsqrtf(q * (1.f / 128.f) + 1e-5f);
                float4 o4;
                o4.x = dx * rstd * ggv.x + bbv.x;
                o4.y = dy * rstd * ggv.y + bbv.y;
                o4.z = dz * rstd * ggv.z + bbv.z;
                o4.w = dw * rstd * ggv.w + bbv.w;
                if (gm < M) {
                    if (doHalf) {
                        __half2 h0 = __floats2half2_rn(o4.x, o4.y);
                        __half2 h1 = __floats2half2_rn(o4.z, o4.w);
                        uint2 u;
                        u.x = *reinterpret_cast<unsigned*>(&h0);
                        u.y = *reinterpret_cast<unsigned*>(&h1);
                        *(uint2*)(CH + (size_t)gm * NN + lane * 4) = u;
                    } else {
                        *(float4*)(C0 + (size_t)gm * NN + lane * 4) = o4;
                    }
                }
            }
        }
    }
}

// ------- fused aggregation: per-warp (m,z) prologue + weighted accumulate ---------
// one warp per (node, head); fp16 feat gather; output fp16 (GEMM2 A) ---------------
__global__ __launch_bounds__(128) void k_agg(const float* __restrict__ bgat) {
    int n = blockIdx.x;
    int h = threadIdx.x >> 5, lane = threadIdx.x & 31;
    int beg = g_rowptr[n], end = g_rowptr[n + 1];
    float ern = g_er[n * 4 + h];

    // phase 1: softmax max & denominator
    float m = -1e30f, z = 0.f;
    for (int e = beg + lane; e < end; e += 32) {
        int s = g_csrsrc[e];
        float v = g_el[s * 4 + h] + ern;
        v = v > 0.f ? v : 0.2f * v;
        float M = fmaxf(m, v);
        z = z * __expf(m - M) + __expf(v - M);
        m = M;
    }
    #pragma unroll
    for (int o = 16; o; o >>= 1) {
        float mo = __shfl_xor_sync(0xffffffffu, m, o);
        float zo = __shfl_xor_sync(0xffffffffu, z, o);
        float M = fmaxf(m, mo);
        z = z * __expf(m - M) + zo * __expf(mo - M);
        m = M;
    }
    float iz = 1.f / fmaxf(z, 1e-20f);

    // phase 2: weighted accumulate
    const __half* fbase = g_featH + h * Dd + lane * 4;
    float4 acc = make_float4(0.f, 0.f, 0.f, 0.f);
    int e = beg;
    for (; e + 4 <= end; e += 4) {
        int s0 = g_csrsrc[e + 0];
        int s1 = g_csrsrc[e + 1];
        int s2 = g_csrsrc[e + 2];
        int s3 = g_csrsrc[e + 3];
        float v0 = g_el[s0 * 4 + h] + ern;
        float v1 = g_el[s1 * 4 + h] + ern;
        float v2 = g_el[s2 * 4 + h] + ern;
        float v3 = g_el[s3 * 4 + h] + ern;
        uint2 u0 = *(const uint2*)(fbase + (size_t)s0 * HDd);
        uint2 u1 = *(const uint2*)(fbase + (size_t)s1 * HDd);
        uint2 u2 = *(const uint2*)(fbase + (size_t)s2 * HDd);
        uint2 u3 = *(const uint2*)(fbase + (size_t)s3 * HDd);
        v0 = v0 > 0.f ? v0 : 0.2f * v0;
        v1 = v1 > 0.f ? v1 : 0.2f * v1;
        v2 = v2 > 0.f ? v2 : 0.2f * v2;
        v3 = v3 > 0.f ? v3 : 0.2f * v3;
        float w0 = __expf(v0 - m), w1 = __expf(v1 - m);
        float w2 = __expf(v2 - m), w3 = __expf(v3 - m);
        float2 a0 = __half22float2(*(__half2*)&u0.x), b0 = __half22float2(*(__half2*)&u0.y);
        float2 a1 = __half22float2(*(__half2*)&u1.x), b1 = __half22float2(*(__half2*)&u1.y);
        float2 a2 = __half22float2(*(__half2*)&u2.x), b2 = __half22float2(*(__half2*)&u2.y);
        float2 a3 = __half22float2(*(__half2*)&u3.x), b3 = __half22float2(*(__half2*)&u3.y);
        acc.x += w0 * a0.x + w1 * a1.x + w2 * a2.x + w3 * a3.x;
        acc.y += w0 * a0.y + w1 * a1.y + w2 * a2.y + w3 * a3.y;
        acc.z += w0 * b0.x + w1 * b1.x + w2 * b2.x + w3 * b3.x;
        acc.w += w0 * b0.y + w1 * b1.y + w2 * b2.y + w3 * b3.y;
    }
    for (; e < end; e++) {
        int s = g_csrsrc[e];
        float v = g_el[s * 4 + h] + ern;
        v = v > 0.f ? v : 0.2f * v;
        float w = __expf(v - m);
        uint2 u = *(const uint2*)(fbase + (size_t)s * HDd);
        float2 a = __half22float2(*(__half2*)&u.x), b = __half22float2(*(__half2*)&u.y);
        acc.x += w * a.x; acc.y += w * a.y; acc.z += w * b.x; acc.w += w * b.y;
    }

    size_t off = (size_t)n * HDd + h * Dd + lane * 4;
    float4 r = *(const float4*)(g_res + off);
    float4 bg = *(const float4*)(bgat + h * Dd + lane * 4);
    float4 o;
    o.x = acc.x * iz + r.x + bg.x;
    o.y = acc.y * iz + r.y + bg.y;
    o.z = acc.z * iz + r.z + bg.z;
    o.w = acc.w * iz + r.w + bg.w;
    o.x = o.x > 0.f ? o.x : 0.01f * o.x;
    o.y = o.y > 0.f ? o.y : 0.01f * o.y;
    o.z = o.z > 0.f ? o.z : 0.01f * o.z;
    o.w = o.w > 0.f ? o.w : 0.01f * o.w;
    __half2 h0 = __floats2half2_rn(o.x, o.y);
    __half2 h1 = __floats2half2_rn(o.z, o.w);
    uint2 u;
    u.x = *reinterpret_cast<unsigned*>(&h0);
    u.y = *reinterpret_cast<unsigned*>(&h1);
    *(uint2*)(g_resH + off) = u;
}

// ---------------- launch ----------------
extern "C" void kernel_launch(void* const* d_in, const int* in_sizes, int n_in,
                              void* d_out, int out_size)
{
    const float* features = (const float*)d_in[0];
    const int*   src      = (const int*)  d_in[1];
    const int*   dst      = (const int*)  d_in[2];
    const float* W_fc     = (const float*)d_in[3];
    const float* attn_l   = (const float*)d_in[4];
    const float* attn_r   = (const float*)d_in[5];
    const float* W_res    = (const float*)d_in[6];
    const float* b_gat    = (const float*)d_in[7];
    const float* W_nrm    = (const float*)d_in[8];
    const float* b_nrm    = (const float*)d_in[9];
    const float* ln_g     = (const float*)d_in[10];
    const float* ln_b     = (const float*)d_in[11];
    float* out = (float*)d_out;

    float *res;
    __half *xh0, *xhA, *xhB, *wh, *resH;
    cudaGetSymbolAddress((void**)&res,  g_res);
    cudaGetSymbolAddress((void**)&xh0,  g_xh0);
    cudaGetSymbolAddress((void**)&xhA,  g_xhA);
    cudaGetSymbolAddress((void**)&xhB,  g_xhB);
    cudaGetSymbolAddress((void**)&wh,   g_wh);
    cudaGetSymbolAddress((void**)&resH, g_resH);

    // preamble (fp16 convert + zero), count, scan -> dual GEMM is launch #4 for ncu
    k_pre<<<(NFEAT + 255) / 256, 256>>>(W_fc, W_res, W_nrm, features);
    k_count<<<(Ee + 255) / 256, 256>>>(dst);
    k_scan<<<1, 1024>>>();

    const int gy = (Nn + 127) / 128;   // 391

    const __half* xin = xh0;
    for (int l = 0; l < Ll; l++) {
        const __half* Wf = wh + (size_t)l * WSZ;
        const __half* Wr = wh + (size_t)(Ll + l) * WSZ;
        const __half* Wn = wh + (size_t)(2 * Ll + l) * WSZ;

        // fused: featH(fp16) + el/er = xin@Wf ; res(fp32) = xin@Wr
        dim3 g1(2 * (HDd / 128), gy);
        gemm_h<Dd, HDd / 128, 0><<<g1, 256>>>(
            xin, Wf, Wr, res, nullptr, Nn,
            attn_l + l * Hh * Dd, attn_r + l * Hh * Dd, nullptr, 0);

        if (l == 0) k_fill<<<(Ee + 255) / 256, 256>>>(src, dst);

        k_agg<<<Nn, 128>>>(b_gat + l * HDd);

        // xout = layernorm(resH @ Wn + b_nrm), fused LN epilogue
        dim3 g2(1, gy);
        if (l == Ll - 1) {
            gemm_h<HDd, 1, 1><<<g2, 256>>>(
                resH, Wn, nullptr, out, nullptr, Nn,
                b_nrm + l * Dd, ln_g + l * Dd, ln_b + l * Dd, 0);
        } else {
            __half* xout = (l & 1) ? xhB : xhA;
            gemm_h<HDd, 1, 1><<<g2, 256>>>(
                resH, Wn, nullptr, nullptr, xout, Nn,
                b_nrm + l * Dd, ln_g + l * Dd, ln_b + l * Dd, 1);
            xin = xout;
        }
    }
}

// round 11
// speedup vs baseline: 2.1854x; 1.6837x over previous
#include <cuda_runtime.h>
#include <cuda_fp16.h>
#include <mma.h>
#include <cstdint>
using namespace nvcuda;

#define Nn 50000
#define Ee 800000
#define Hh 4
#define Dd 128
#define HDd 512
#define Ll 4
#define MPAD 50048   // 391*128, pads fp32 res buffer so GEMM1 res stores are unguarded

#define WSZ (Dd * HDd)          // 65536 per weight matrix
#define NWEIGHT (3 * Ll * WSZ)  // 786432
#define NFEAT (Nn * Dd)         // 6.4M

// dual-GEMM static smem ring (halves): 4 A bufs (128x24) + 4 B bufs (16x136)
#define ASTRIDE_H 3072          // 128*24
#define BBASE_H   12288         // 4*ASTRIDE_H
#define BSTRIDE_H 2176          // 16*136
#define SMHALVES  20992         // 41984 B; epilogue reuses as 64x132 floats

// gemm_ln smem: stage = 4*(64*24) + 4*(16*136) halves = 29696 B; epi 64*132 f = 33792 B
#define LN_ASTRIDE 1536         // 64*24 halves
#define LN_BBASE   6144
#define LN_SMBYTES 34048

// ---------------- scratch (static device memory; no allocations) ----------------
__device__ __align__(16) __half g_featH[(size_t)Nn * HDd];  // fp16 feat (k_agg payload)
__device__ __align__(16) float  g_res  [(size_t)MPAD * HDd]; // fp32 x@Wr (k_agg residual)
__device__ __align__(16) __half g_resH [(size_t)Nn * HDd];  // fp16 k_agg out (GEMM2 A)
__device__ __align__(16) float  g_el[Nn * Hh];
__device__ __align__(16) float  g_er[Nn * Hh];
__device__ __align__(16) __half g_xh0[(size_t)Nn * Dd];     // fp16 features
__device__ __align__(16) __half g_xhA[(size_t)Nn * Dd];
__device__ __align__(16) __half g_xhB[(size_t)Nn * Dd];
__device__ __align__(16) __half g_wh[NWEIGHT];              // fp16 weights
__device__ int g_deg[Nn];
__device__ int g_rowptr[Nn + 1];
__device__ int g_cursor[Nn];
__device__ int g_csrsrc[Ee];

// ---------------- preamble: convert weights+features to fp16, zero deg -------------
__global__ void k_pre(const float* __restrict__ Wf, const float* __restrict__ Wr,
                      const float* __restrict__ Wn, const float* __restrict__ feats)
{
    int i = blockIdx.x * blockDim.x + threadIdx.x;
    if (i < NFEAT) g_xh0[i] = __float2half_rn(feats[i]);
    if (i < Ll * WSZ) {
        g_wh[i]                = __float2half_rn(Wf[i]);
        g_wh[Ll * WSZ + i]     = __float2half_rn(Wr[i]);
        g_wh[2 * Ll * WSZ + i] = __float2half_rn(Wn[i]);
    }
    if (i < Nn) g_deg[i] = 0;
}

__global__ void k_count(const int* __restrict__ dst) {
    int i = blockIdx.x * blockDim.x + threadIdx.x;
    if (i < Ee) atomicAdd(&g_deg[dst[i]], 1);
}

// single-block exclusive scan over g_deg -> g_rowptr (+ cursor init fused)
__global__ void k_scan() {
    __shared__ int sh[1024];
    __shared__ int carry;
    int t = threadIdx.x;
    if (t == 0) { carry = 0; g_rowptr[0] = 0; }
    __syncthreads();
    for (int base = 0; base < Nn; base += 1024) {
        int i = base + t;
        int v = (i < Nn) ? g_deg[i] : 0;
        sh[t] = v;
        __syncthreads();
        #pragma unroll
        for (int off = 1; off < 1024; off <<= 1) {
            int tv = (t >= off) ? sh[t - off] : 0;
            __syncthreads();
            sh[t] += tv;
            __syncthreads();
        }
        int incl = sh[t];
        int c = carry;
        __syncthreads();
        if (i < Nn) {
            g_rowptr[i + 1] = c + incl;
            g_cursor[i] = c + incl - v;
        }
        if (t == 1023) carry = c + incl;
        __syncthreads();
    }
}

__global__ void k_fill(const int* __restrict__ src, const int* __restrict__ dst) {
    int i = blockIdx.x * blockDim.x + threadIdx.x;
    if (i < Ee) {
        int p = atomicAdd(&g_cursor[dst[i]], 1);
        g_csrsrc[p] = src[i];
    }
}

// ---------------- cp.async helper ----------------
__device__ __forceinline__ void cp16(uint32_t dst, const void* src, bool pred) {
    int sz = pred ? 16 : 0;
    asm volatile("cp.async.cg.shared.global [%0], [%1], 16, %2;\n"
                 :: "r"(dst), "l"(src), "r"(sz));
}

// ---------------- dual fp16 GEMM (m16n16k16), CTA 128x128, BK=16, 4-stage ---------
// res half (bx>=TPH): fp32 store to padded C0.
// feat half (bx<TPH): epilogue computes el/er (p0/p1) + fp16 feat store.
template<int K, int TPH>
__global__ __launch_bounds__(256) void gemm_h(
    const __half* __restrict__ A,
    const __half* __restrict__ B0, const __half* __restrict__ B1,
    float* __restrict__ C0, int M,
    const float* __restrict__ p0, const float* __restrict__ p1)
{
    constexpr int NN = TPH * 128;
    __shared__ __align__(16) __half smh[SMHALVES];
    float* smf = reinterpret_cast<float*>(smh);

    const int tid = threadIdx.x;
    const int warp = tid >> 5;
    const int lane = tid & 31;
    const int wm = warp & 1, wn = warp >> 1;
    const int row0 = blockIdx.y * 128;

    int bx = blockIdx.x;
    bool isFeatHalf = (bx < TPH);
    const __half* B = B0;
    if (!isFeatHalf) { bx -= TPH; B = B1; }
    const int col0 = bx * 128;

    wmma::fragment<wmma::accumulator, 16, 16, 16, float> acc[4][2];
    #pragma unroll
    for (int i = 0; i < 4; i++)
        #pragma unroll
        for (int j = 0; j < 2; j++)
            wmma::fill_fragment(acc[i][j], 0.0f);

    constexpr int KT = K >> 4;

    auto stage = [&](int buf, int k0) {
        __half* As = smh + buf * ASTRIDE_H;
        __half* Bs = smh + BBASE_H + buf * BSTRIDE_H;
        {
            int r = tid >> 1, q = tid & 1;
            int gm = row0 + r;
            const __half* srcp = A + (size_t)gm * K + k0 + q * 8;
            uint32_t d = (uint32_t)__cvta_generic_to_shared(&As[r * 24 + q * 8]);
            cp16(d, srcp, gm < M);
        }
        {
            int r = tid >> 4, q = tid & 15;
            const __half* srcp = B + (size_t)(k0 + r) * NN + col0 + q * 8;
            uint32_t d = (uint32_t)__cvta_generic_to_shared(&Bs[r * 136 + q * 8]);
            cp16(d, srcp, true);
        }
        asm volatile("cp.async.commit_group;");
    };

    stage(0, 0);
    stage(1, 16);
    stage(2, 32);

    for (int kt = 0; kt < KT; kt++) {
        if (kt + 3 < KT) asm volatile("cp.async.wait_group 2;");
        else             asm volatile("cp.async.wait_group 0;");
        __syncthreads();

        int buf = kt & 3;
        const __half* As = smh + buf * ASTRIDE_H;
        const __half* Bs = smh + BBASE_H + buf * BSTRIDE_H;
        wmma::fragment<wmma::matrix_a, 16, 16, 16, __half, wmma::row_major> a[4];
        wmma::fragment<wmma::matrix_b, 16, 16, 16, __half, wmma::row_major> b[2];
        #pragma unroll
        for (int i = 0; i < 4; i++)
            wmma::load_matrix_sync(a[i], As + (wm * 64 + i * 16) * 24, 24);
        #pragma unroll
        for (int j = 0; j < 2; j++)
            wmma::load_matrix_sync(b[j], Bs + wn * 32 + j * 16, 136);
        #pragma unroll
        for (int i = 0; i < 4; i++)
            #pragma unroll
            for (int j = 0; j < 2; j++)
                wmma::mma_sync(acc[i][j], a[i], b[j], acc[i][j]);

        if (kt + 3 < KT) stage((kt + 3) & 3, (kt + 3) << 4);
    }

    if (!isFeatHalf) {
        #pragma unroll
        for (int i = 0; i < 4; i++)
            #pragma unroll
            for (int j = 0; j < 2; j++)
                wmma::store_matrix_sync(
                    C0 + (size_t)(row0 + wm * 64 + i * 16) * NN + col0 + wn * 32 + j * 16,
                    acc[i][j], NN, wmma::mem_row_major);
    } else {
        // attn coefficients + fp16 feat store (head h == bx)
        float* sC = smf;   // 64 x 132 floats
        float4 alv = *(const float4*)(p0 + col0 + lane * 4);
        float4 arv = *(const float4*)(p1 + col0 + lane * 4);
        __syncthreads();
        #pragma unroll
        for (int p = 0; p < 2; p++) {
            if (wm == p) {
                #pragma unroll
                for (int i = 0; i < 4; i++)
                    #pragma unroll
                    for (int j = 0; j < 2; j++)
                        wmma::store_matrix_sync(
                            sC + (size_t)(i * 16) * 132 + wn * 32 + j * 16,
                            acc[i][j], 132, wmma::mem_row_major);
            }
            __syncthreads();
            #pragma unroll
            for (int rr = 0; rr < 8; rr++) {
                int lr = warp * 8 + rr;
                int gm = row0 + p * 64 + lr;
                float4 v = *(const float4*)(sC + (size_t)lr * 132 + lane * 4);
                bool valid = gm < M;
                if (valid) {
                    __half2 h0 = __floats2half2_rn(v.x, v.y);
                    __half2 h1 = __floats2half2_rn(v.z, v.w);
                    uint2 u;
                    u.x = *reinterpret_cast<unsigned*>(&h0);
                    u.y = *reinterpret_cast<unsigned*>(&h1);
                    *(uint2*)(g_featH + (size_t)gm * HDd + col0 + lane * 4) = u;
                }
                float sl = v.x * alv.x + v.y * alv.y + v.z * alv.z + v.w * alv.w;
                float sr = v.x * arv.x + v.y * arv.y + v.z * arv.z + v.w * arv.w;
                #pragma unroll
                for (int o = 16; o; o >>= 1) {
                    sl += __shfl_xor_sync(0xffffffffu, sl, o);
                    sr += __shfl_xor_sync(0xffffffffu, sr, o);
                }
                if (lane == 0 && valid) {
                    g_el[gm * Hh + bx] = sl;
                    g_er[gm * Hh + bx] = sr;
                }
            }
            __syncthreads();
        }
    }
}

// ---------------- GEMM2 + LN: CTA 64x128, 8 warps (2m x 4n), warp 32x32 -----------
template<int K>
__global__ __launch_bounds__(256) void gemm_ln(
    const __half* __restrict__ A, const __half* __restrict__ B,
    float* __restrict__ C0, __half* __restrict__ CH, int M,
    const float* __restrict__ bn, const float* __restrict__ lng,
    const float* __restrict__ lnb, int doHalf)
{
    constexpr int NN = 128;
    __shared__ __align__(16) char smraw[LN_SMBYTES];
    __half* smh = reinterpret_cast<__half*>(smraw);
    float* smf = reinterpret_cast<float*>(smraw);

    const int tid = threadIdx.x;
    const int warp = tid >> 5;
    const int lane = tid & 31;
    const int wm = warp & 1, wn = warp >> 1;
    const int row0 = blockIdx.x * 64;

    wmma::fragment<wmma::accumulator, 16, 16, 16, float> acc[2][2];
    #pragma unroll
    for (int i = 0; i < 2; i++)
        #pragma unroll
        for (int j = 0; j < 2; j++)
            wmma::fill_fragment(acc[i][j], 0.0f);

    constexpr int KT = K >> 4;

    auto stage = [&](int buf, int k0) {
        __half* As = smh + buf * LN_ASTRIDE;
        __half* Bs = smh + LN_BBASE + buf * BSTRIDE_H;
        if (tid < 128) {   // A: 64 rows x 16 halves = 128 x 16B
            int r = tid >> 1, q = tid & 1;
            int gm = row0 + r;
            const __half* srcp = A + (size_t)gm * K + k0 + q * 8;
            uint32_t d = (uint32_t)__cvta_generic_to_shared(&As[r * 24 + q * 8]);
            cp16(d, srcp, gm < M);
        }
        {   // B: 16 rows x 128 halves = 256 x 16B
            int r = tid >> 4, q = tid & 15;
            const __half* srcp = B + (size_t)(k0 + r) * NN + q * 8;
            uint32_t d = (uint32_t)__cvta_generic_to_shared(&Bs[r * 136 + q * 8]);
            cp16(d, srcp, true);
        }
        asm volatile("cp.async.commit_group;");
    };

    stage(0, 0);
    stage(1, 16);
    stage(2, 32);

    for (int kt = 0; kt < KT; kt++) {
        if (kt + 3 < KT) asm volatile("cp.async.wait_group 2;");
        else             asm volatile("cp.async.wait_group 0;");
        __syncthreads();

        int buf = kt & 3;
        const __half* As = smh + buf * LN_ASTRIDE;
        const __half* Bs = smh + LN_BBASE + buf * BSTRIDE_H;
        wmma::fragment<wmma::matrix_a, 16, 16, 16, __half, wmma::row_major> a[2];
        wmma::fragment<wmma::matrix_b, 16, 16, 16, __half, wmma::row_major> b[2];
        #pragma unroll
        for (int i = 0; i < 2; i++)
            wmma::load_matrix_sync(a[i], As + (wm * 32 + i * 16) * 24, 24);
        #pragma unroll
        for (int j = 0; j < 2; j++)
            wmma::load_matrix_sync(b[j], Bs + wn * 32 + j * 16, 136);
        #pragma unroll
        for (int i = 0; i < 2; i++)
            #pragma unroll
            for (int j = 0; j < 2; j++)
                wmma::mma_sync(acc[i][j], a[i], b[j], acc[i][j]);

        if (kt + 3 < KT) stage((kt + 3) & 3, (kt + 3) << 4);
    }

    // fused bias + layernorm epilogue (single 64-row phase)
    __syncthreads();
    #pragma unroll
    for (int i = 0; i < 2; i++)
        #pragma unroll
        for (int j = 0; j < 2; j++)
            wmma::store_matrix_sync(
                smf + (size_t)(wm * 32 + i * 16) * 132 + wn * 32 + j * 16,
                acc[i][j], 132, wmma::mem_row_major);
    __syncthreads();

    float4 bnv = ((const float4*)bn)[lane];
    float4 ggv = ((const float4*)lng)[lane];
    float4 bbv = ((const float4*)lnb)[lane];
    #pragma unroll
    for (int rr = 0; rr < 8; rr++) {
        int lr = warp * 8 + rr;
        int gm = row0 + lr;
        float4 v = *(const float4*)(smf + (size_t)lr * 132 + lane * 4);
        v.x += bnv.x; v.y += bnv.y; v.z += bnv.z; v.w += bnv.w;
        float s = v.x + v.y + v.z + v.w;
        #pragma unroll
        for (int o = 16; o; o >>= 1) s += __shfl_xor_sync(0xffffffffu, s, o);
        float mu = s * (1.f / 128.f);
        float dx = v.x - mu, dy = v.y - mu, dz = v.z - mu, dw = v.w - mu;
        float q = dx * dx + dy * dy + dz * dz + dw * dw;
        #pragma unroll
        for (int o = 16; o; o >>= 1) q += __shfl_xor_sync(0xffffffffu, q, o);
        float rstd = rsqrtf(q * (1.f / 128.f) + 1e-5f);
        float4 o4;
        o4.x = dx * rstd * ggv.x + bbv.x;
        o4.y = dy * rstd * ggv.y + bbv.y;
        o4.z = dz * rstd * ggv.z + bbv.z;
        o4.w = dw * rstd * ggv.w + bbv.w;
        if (gm < M) {
            if (doHalf) {
                __half2 h0 = __floats2half2_rn(o4.x, o4.y);
                __half2 h1 = __floats2half2_rn(o4.z, o4.w);
                uint2 u;
                u.x = *reinterpret_cast<unsigned*>(&h0);
                u.y = *reinterpret_cast<unsigned*>(&h1);
                *(uint2*)(CH + (size_t)gm * NN + lane * 4) = u;
            } else {
                *(float4*)(C0 + (size_t)gm * NN + lane * 4) = o4;
            }
        }
    }
}

// ------- aggregation: smem edge staging, one exp per (edge,head) -------------------
// block = node (128 threads); fast path deg<=128, per-warp fallback otherwise
__global__ __launch_bounds__(128) void k_agg(const float* __restrict__ bgat) {
    __shared__ int   s_src[128];
    __shared__ float s_v[128 * 4];

    int n = blockIdx.x;
    int tid = threadIdx.x;
    int h = tid >> 5, lane = tid & 31;
    int beg = g_rowptr[n], end = g_rowptr[n + 1];
    int deg = end - beg;

    float4 acc = make_float4(0.f, 0.f, 0.f, 0.f);
    float iz;
    const __half* fbase = g_featH + h * Dd + lane * 4;

    if (deg <= 128) {
        // phase 1: all threads, one edge each -> logits for all 4 heads into smem
        if (tid < deg) {
            int s = g_csrsrc[beg + tid];
            s_src[tid] = s;
            float4 el = *(const float4*)(g_el + s * 4);
            float4 er = *(const float4*)(g_er + n * 4);
            float v0 = el.x + er.x; v0 = v0 > 0.f ? v0 : 0.2f * v0;
            float v1 = el.y + er.y; v1 = v1 > 0.f ? v1 : 0.2f * v1;
            float v2 = el.z + er.z; v2 = v2 > 0.f ? v2 : 0.2f * v2;
            float v3 = el.w + er.w; v3 = v3 > 0.f ? v3 : 0.2f * v3;
            *(float4*)(s_v + tid * 4) = make_float4(v0, v1, v2, v3);
        }
        __syncthreads();

        // per-warp (head h): max reduce over smem
        float m = -1e30f;
        for (int e = lane; e < deg; e += 32) m = fmaxf(m, s_v[e * 4 + h]);
        #pragma unroll
        for (int o = 16; o; o >>= 1) m = fmaxf(m, __shfl_xor_sync(0xffffffffu, m, o));

        // exp once, write weight back, sum
        float z = 0.f;
        for (int e = lane; e < deg; e += 32) {
            float w = __expf(s_v[e * 4 + h] - m);
            s_v[e * 4 + h] = w;
            z += w;
        }
        #pragma unroll
        for (int o = 16; o; o >>= 1) z += __shfl_xor_sync(0xffffffffu, z, o);
        iz = 1.f / fmaxf(z, 1e-20f);
        __syncwarp();

        // gather: smem weight + one 8B feat load per edge, 4-way unrolled
        int e = 0;
        for (; e + 4 <= deg; e += 4) {
            int s0 = s_src[e + 0], s1 = s_src[e + 1];
            int s2 = s_src[e + 2], s3 = s_src[e + 3];
            float w0 = s_v[(e + 0) * 4 + h], w1 = s_v[(e + 1) * 4 + h];
            float w2 = s_v[(e + 2) * 4 + h], w3 = s_v[(e + 3) * 4 + h];
            uint2 u0 = *(const uint2*)(fbase + (size_t)s0 * HDd);
            uint2 u1 = *(const uint2*)(fbase + (size_t)s1 * HDd);
            uint2 u2 = *(const uint2*)(fbase + (size_t)s2 * HDd);
            uint2 u3 = *(const uint2*)(fbase + (size_t)s3 * HDd);
            float2 a0 = __half22float2(*(__half2*)&u0.x), b0 = __half22float2(*(__half2*)&u0.y);
            float2 a1 = __half22float2(*(__half2*)&u1.x), b1 = __half22float2(*(__half2*)&u1.y);
            float2 a2 = __half22float2(*(__half2*)&u2.x), b2 = __half22float2(*(__half2*)&u2.y);
            float2 a3 = __half22float2(*(__half2*)&u3.x), b3 = __half22float2(*(__half2*)&u3.y);
            acc.x += w0 * a0.x + w1 * a1.x + w2 * a2.x + w3 * a3.x;
            acc.y += w0 * a0.y + w1 * a1.y + w2 * a2.y + w3 * a3.y;
            acc.z += w0 * b0.x + w1 * b1.x + w2 * b2.x + w3 * b3.x;
            acc.w += w0 * b0.y + w1 * b1.y + w2 * b2.y + w3 * b3.y;
        }
        for (; e < deg; e++) {
            int s = s_src[e];
            float w = s_v[e * 4 + h];
            uint2 u = *(const uint2*)(fbase + (size_t)s * HDd);
            float2 a = __half22float2(*(__half2*)&u.x), b = __half22float2(*(__half2*)&u.y);
            acc.x += w * a.x; acc.y += w * a.y; acc.z += w * b.x; acc.w += w * b.y;
        }
    } else {
        // fallback: per-warp two-pass (any degree)
        float ern = g_er[n * 4 + h];
        float m = -1e30f, z = 0.f;
        for (int e = beg + lane; e < end; e += 32) {
            int s = g_csrsrc[e];
            float v = g_el[s * 4 + h] + ern;
            v = v > 0.f ? v : 0.2f * v;
            float M = fmaxf(m, v);
            z = z * __expf(m - M) + __expf(v - M);
            m = M;
        }
        #pragma unroll
        for (int o = 16; o; o >>= 1) {
            float mo = __shfl_xor_sync(0xffffffffu, m, o);
            float zo = __shfl_xor_sync(0xffffffffu, z, o);
            float M = fmaxf(m, mo);
            z = z * __expf(m - M) + zo * __expf(mo - M);
            m = M;
        }
        iz = 1.f / fmaxf(z, 1e-20f);
        for (int e = beg; e < end; e++) {
            int s = g_csrsrc[e];
            float v = g_el[s * 4 + h] + ern;
            v = v > 0.f ? v : 0.2f * v;
            float w = __expf(v - m);
            uint2 u = *(const uint2*)(fbase + (size_t)s * HDd);
            float2 a = __half22float2(*(__half2*)&u.x), b = __half22float2(*(__half2*)&u.y);
            acc.x += w * a.x; acc.y += w * a.y; acc.z += w * b.x; acc.w += w * b.y;
        }
    }

    size_t off = (size_t)n * HDd + h * Dd + lane * 4;
    float4 r = *(const float4*)(g_res + off);
    float4 bg = *(const float4*)(bgat + h * Dd + lane * 4);
    float4 o;
    o.x = acc.x * iz + r.x + bg.x;
    o.y = acc.y * iz + r.y + bg.y;
    o.z = acc.z * iz + r.z + bg.z;
    o.w = acc.w * iz + r.w + bg.w;
    o.x = o.x > 0.f ? o.x : 0.01f * o.x;
    o.y = o.y > 0.f ? o.y : 0.01f * o.y;
    o.z = o.z > 0.f ? o.z : 0.01f * o.z;
    o.w = o.w > 0.f ? o.w : 0.01f * o.w;
    __half2 h0 = __floats2half2_rn(o.x, o.y);
    __half2 h1 = __floats2half2_rn(o.z, o.w);
    uint2 u;
    u.x = *reinterpret_cast<unsigned*>(&h0);
    u.y = *reinterpret_cast<unsigned*>(&h1);
    *(uint2*)(g_resH + off) = u;
}

// ---------------- launch ----------------
extern "C" void kernel_launch(void* const* d_in, const int* in_sizes, int n_in,
                              void* d_out, int out_size)
{
    const float* features = (const float*)d_in[0];
    const int*   src      = (const int*)  d_in[1];
    const int*   dst      = (const int*)  d_in[2];
    const float* W_fc     = (const float*)d_in[3];
    const float* attn_l   = (const float*)d_in[4];
    const float* attn_r   = (const float*)d_in[5];
    const float* W_res    = (const float*)d_in[6];
    const float* b_gat    = (const float*)d_in[7];
    const float* W_nrm    = (const float*)d_in[8];
    const float* b_nrm    = (const float*)d_in[9];
    const float* ln_g     = (const float*)d_in[10];
    const float* ln_b     = (const float*)d_in[11];
    float* out = (float*)d_out;

    float *res;
    __half *xh0, *xhA, *xhB, *wh, *resH;
    cudaGetSymbolAddress((void**)&res,  g_res);
    cudaGetSymbolAddress((void**)&xh0,  g_xh0);
    cudaGetSymbolAddress((void**)&xhA,  g_xhA);
    cudaGetSymbolAddress((void**)&xhB,  g_xhB);
    cudaGetSymbolAddress((void**)&wh,   g_wh);
    cudaGetSymbolAddress((void**)&resH, g_resH);

    // preamble (fp16 convert + zero), count, scan -> dual GEMM is launch #4 for ncu
    k_pre<<<(NFEAT + 255) / 256, 256>>>(W_fc, W_res, W_nrm, features);
    k_count<<<(Ee + 255) / 256, 256>>>(dst);
    k_scan<<<1, 1024>>>();

    const int gy = (Nn + 127) / 128;   // 391
    const int gln = (Nn + 63) / 64;    // 782

    const __half* xin = xh0;
    for (int l = 0; l < Ll; l++) {
        const __half* Wf = wh + (size_t)l * WSZ;
        const __half* Wr = wh + (size_t)(Ll + l) * WSZ;
        const __half* Wn = wh + (size_t)(2 * Ll + l) * WSZ;

        // fused: featH(fp16) + el/er = xin@Wf ; res(fp32) = xin@Wr
        dim3 g1(2 * (HDd / 128), gy);
        gemm_h<Dd, HDd / 128><<<g1, 256>>>(
            xin, Wf, Wr, res, Nn,
            attn_l + l * Hh * Dd, attn_r + l * Hh * Dd);

        if (l == 0) k_fill<<<(Ee + 255) / 256, 256>>>(src, dst);

        k_agg<<<Nn, 128>>>(b_gat + l * HDd);

        // xout = layernorm(resH @ Wn + b_nrm), fused LN epilogue, 64-row tiles
        if (l == Ll - 1) {
            gemm_ln<HDd><<<gln, 256>>>(
                resH, Wn, out, nullptr, Nn,
                b_nrm + l * Dd, ln_g + l * Dd, ln_b + l * Dd, 0);
        } else {
            __half* xout = (l & 1) ? xhB : xhA;
            gemm_ln<HDd><<<gln, 256>>>(
                resH, Wn, nullptr, xout, Nn,
                b_nrm + l * Dd, ln_g + l * Dd, ln_b + l * Dd, 1);
            xin = xout;
        }
    }
}

// round 12
// speedup vs baseline: 2.2847x; 1.0454x over previous
#include <cuda_runtime.h>
#include <cuda_fp16.h>
#include <mma.h>
#include <cstdint>
using namespace nvcuda;

#define Nn 50000
#define Ee 800000
#define Hh 4
#define Dd 128
#define HDd 512
#define Ll 4

#define WSZ (Dd * HDd)          // 65536 per weight matrix
#define NWEIGHT (3 * Ll * WSZ)  // 786432
#define NFEAT (Nn * Dd)         // 6.4M

// dual-GEMM static smem ring (halves): 4 A bufs (128x24) + 4 B bufs (16x136)
#define ASTRIDE_H 3072          // 128*24
#define BBASE_H   12288         // 4*ASTRIDE_H
#define BSTRIDE_H 2176          // 16*136
#define SMHALVES  20992         // 41984 B; epilogue reuses as 64x132 floats

// gemm_ln smem: stage = 4*(64*24) + 4*(16*136) halves = 29696 B; epi 64*132 f = 33792 B
#define LN_ASTRIDE 1536         // 64*24 halves
#define LN_BBASE   6144
#define LN_SMBYTES 34048

// ---------------- scratch (static device memory; no allocations) ----------------
__device__ __align__(16) __half g_featH[(size_t)Nn * HDd];  // fp16 feat (k_agg payload)
__device__ __align__(16) __half g_resR [(size_t)Nn * HDd];  // fp16 x@Wr (k_agg residual)
__device__ __align__(16) __half g_resH [(size_t)Nn * HDd];  // fp16 k_agg out (GEMM2 A)
__device__ __align__(16) float  g_el[Nn * Hh];
__device__ __align__(16) float  g_er[Nn * Hh];
__device__ __align__(16) __half g_xh0[(size_t)Nn * Dd];     // fp16 features
__device__ __align__(16) __half g_xhA[(size_t)Nn * Dd];
__device__ __align__(16) __half g_xhB[(size_t)Nn * Dd];
__device__ __align__(16) __half g_wh[NWEIGHT];              // fp16 weights
__device__ int g_deg[Nn];
__device__ int g_rowptr[Nn + 1];
__device__ int g_cursor[Nn];
__device__ int g_csrsrc[Ee];

// ---------------- preamble: convert weights+features to fp16, zero deg -------------
__global__ void k_pre(const float* __restrict__ Wf, const float* __restrict__ Wr,
                      const float* __restrict__ Wn, const float* __restrict__ feats)
{
    int i = blockIdx.x * blockDim.x + threadIdx.x;
    if (i < NFEAT) g_xh0[i] = __float2half_rn(feats[i]);
    if (i < Ll * WSZ) {
        g_wh[i]                = __float2half_rn(Wf[i]);
        g_wh[Ll * WSZ + i]     = __float2half_rn(Wr[i]);
        g_wh[2 * Ll * WSZ + i] = __float2half_rn(Wn[i]);
    }
    if (i < Nn) g_deg[i] = 0;
}

__global__ void k_count(const int* __restrict__ dst) {
    int i = blockIdx.x * blockDim.x + threadIdx.x;
    if (i < Ee) atomicAdd(&g_deg[dst[i]], 1);
}

// single-block exclusive scan over g_deg -> g_rowptr (+ cursor init fused)
__global__ void k_scan() {
    __shared__ int sh[1024];
    __shared__ int carry;
    int t = threadIdx.x;
    if (t == 0) { carry = 0; g_rowptr[0] = 0; }
    __syncthreads();
    for (int base = 0; base < Nn; base += 1024) {
        int i = base + t;
        int v = (i < Nn) ? g_deg[i] : 0;
        sh[t] = v;
        __syncthreads();
        #pragma unroll
        for (int off = 1; off < 1024; off <<= 1) {
            int tv = (t >= off) ? sh[t - off] : 0;
            __syncthreads();
            sh[t] += tv;
            __syncthreads();
        }
        int incl = sh[t];
        int c = carry;
        __syncthreads();
        if (i < Nn) {
            g_rowptr[i + 1] = c + incl;
            g_cursor[i] = c + incl - v;
        }
        if (t == 1023) carry = c + incl;
        __syncthreads();
    }
}

__global__ void k_fill(const int* __restrict__ src, const int* __restrict__ dst) {
    int i = blockIdx.x * blockDim.x + threadIdx.x;
    if (i < Ee) {
        int p = atomicAdd(&g_cursor[dst[i]], 1);
        g_csrsrc[p] = src[i];
    }
}

// ---------------- cp.async helper ----------------
__device__ __forceinline__ void cp16(uint32_t dst, const void* src, bool pred) {
    int sz = pred ? 16 : 0;
    asm volatile("cp.async.cg.shared.global [%0], [%1], 16, %2;\n"
                 :: "r"(dst), "l"(src), "r"(sz));
}

__device__ __forceinline__ uint2 pack_h4(float x, float y, float z, float w) {
    __half2 h0 = __floats2half2_rn(x, y);
    __half2 h1 = __floats2half2_rn(z, w);
    uint2 u;
    u.x = *reinterpret_cast<unsigned*>(&h0);
    u.y = *reinterpret_cast<unsigned*>(&h1);
    return u;
}

// ---------------- dual fp16 GEMM (m16n16k16), CTA 128x128, BK=16, 4-stage ---------
// Both halves epilogue via smem -> fp16 stores (guarded).
// feat half (bx<TPH): also computes attn el/er (head h == bx).
template<int K, int TPH>
__global__ __launch_bounds__(256) void gemm_h(
    const __half* __restrict__ A,
    const __half* __restrict__ B0, const __half* __restrict__ B1,
    int M, const float* __restrict__ p0, const float* __restrict__ p1)
{
    constexpr int NN = TPH * 128;
    __shared__ __align__(16) __half smh[SMHALVES];
    float* smf = reinterpret_cast<float*>(smh);

    const int tid = threadIdx.x;
    const int warp = tid >> 5;
    const int lane = tid & 31;
    const int wm = warp & 1, wn = warp >> 1;
    const int row0 = blockIdx.y * 128;

    int bx = blockIdx.x;
    bool isFeatHalf = (bx < TPH);
    const __half* B = B0;
    if (!isFeatHalf) { bx -= TPH; B = B1; }
    const int col0 = bx * 128;

    wmma::fragment<wmma::accumulator, 16, 16, 16, float> acc[4][2];
    #pragma unroll
    for (int i = 0; i < 4; i++)
        #pragma unroll
        for (int j = 0; j < 2; j++)
            wmma::fill_fragment(acc[i][j], 0.0f);

    constexpr int KT = K >> 4;

    auto stage = [&](int buf, int k0) {
        __half* As = smh + buf * ASTRIDE_H;
        __half* Bs = smh + BBASE_H + buf * BSTRIDE_H;
        {
            int r = tid >> 1, q = tid & 1;
            int gm = row0 + r;
            const __half* srcp = A + (size_t)gm * K + k0 + q * 8;
            uint32_t d = (uint32_t)__cvta_generic_to_shared(&As[r * 24 + q * 8]);
            cp16(d, srcp, gm < M);
        }
        {
            int r = tid >> 4, q = tid & 15;
            const __half* srcp = B + (size_t)(k0 + r) * NN + col0 + q * 8;
            uint32_t d = (uint32_t)__cvta_generic_to_shared(&Bs[r * 136 + q * 8]);
            cp16(d, srcp, true);
        }
        asm volatile("cp.async.commit_group;");
    };

    stage(0, 0);
    stage(1, 16);
    stage(2, 32);

    for (int kt = 0; kt < KT; kt++) {
        if (kt + 3 < KT) asm volatile("cp.async.wait_group 2;");
        else             asm volatile("cp.async.wait_group 0;");
        __syncthreads();

        int buf = kt & 3;
        const __half* As = smh + buf * ASTRIDE_H;
        const __half* Bs = smh + BBASE_H + buf * BSTRIDE_H;
        wmma::fragment<wmma::matrix_a, 16, 16, 16, __half, wmma::row_major> a[4];
        wmma::fragment<wmma::matrix_b, 16, 16, 16, __half, wmma::row_major> b[2];
        #pragma unroll
        for (int i = 0; i < 4; i++)
            wmma::load_matrix_sync(a[i], As + (wm * 64 + i * 16) * 24, 24);
        #pragma unroll
        for (int j = 0; j < 2; j++)
            wmma::load_matrix_sync(b[j], Bs + wn * 32 + j * 16, 136);
        #pragma unroll
        for (int i = 0; i < 4; i++)
            #pragma unroll
            for (int j = 0; j < 2; j++)
                wmma::mma_sync(acc[i][j], a[i], b[j], acc[i][j]);

        if (kt + 3 < KT) stage((kt + 3) & 3, (kt + 3) << 4);
    }

    // epilogue: acc -> smem (two 64-row phases) -> fp16 global (+ el/er on feat half)
    float* sC = smf;   // 64 x 132 floats
    float4 alv, arv;
    if (isFeatHalf) {
        alv = *(const float4*)(p0 + col0 + lane * 4);
        arv = *(const float4*)(p1 + col0 + lane * 4);
    }
    __half* outbase = isFeatHalf ? g_featH : g_resR;
    __syncthreads();
    #pragma unroll
    for (int p = 0; p < 2; p++) {
        if (wm == p) {
            #pragma unroll
            for (int i = 0; i < 4; i++)
                #pragma unroll
                for (int j = 0; j < 2; j++)
                    wmma::store_matrix_sync(
                        sC + (size_t)(i * 16) * 132 + wn * 32 + j * 16,
                        acc[i][j], 132, wmma::mem_row_major);
        }
        __syncthreads();
        #pragma unroll
        for (int rr = 0; rr < 8; rr++) {
            int lr = warp * 8 + rr;
            int gm = row0 + p * 64 + lr;
            float4 v = *(const float4*)(sC + (size_t)lr * 132 + lane * 4);
            bool valid = gm < M;
            if (valid) {
                uint2 u = pack_h4(v.x, v.y, v.z, v.w);
                *(uint2*)(outbase + (size_t)gm * HDd + col0 + lane * 4) = u;
            }
            if (isFeatHalf) {
                float sl = v.x * alv.x + v.y * alv.y + v.z * alv.z + v.w * alv.w;
                float sr = v.x * arv.x + v.y * arv.y + v.z * arv.z + v.w * arv.w;
                #pragma unroll
                for (int o = 16; o; o >>= 1) {
                    sl += __shfl_xor_sync(0xffffffffu, sl, o);
                    sr += __shfl_xor_sync(0xffffffffu, sr, o);
                }
                if (lane == 0 && valid) {
                    g_el[gm * Hh + bx] = sl;
                    g_er[gm * Hh + bx] = sr;
                }
            }
        }
        __syncthreads();
    }
}

// ---------------- GEMM2 + LN: CTA 64x128, 8 warps (2m x 4n), warp 32x32 -----------
template<int K>
__global__ __launch_bounds__(256) void gemm_ln(
    const __half* __restrict__ A, const __half* __restrict__ B,
    float* __restrict__ C0, __half* __restrict__ CH, int M,
    const float* __restrict__ bn, const float* __restrict__ lng,
    const float* __restrict__ lnb, int doHalf)
{
    constexpr int NN = 128;
    __shared__ __align__(16) char smraw[LN_SMBYTES];
    __half* smh = reinterpret_cast<__half*>(smraw);
    float* smf = reinterpret_cast<float*>(smraw);

    const int tid = threadIdx.x;
    const int warp = tid >> 5;
    const int lane = tid & 31;
    const int wm = warp & 1, wn = warp >> 1;
    const int row0 = blockIdx.x * 64;

    wmma::fragment<wmma::accumulator, 16, 16, 16, float> acc[2][2];
    #pragma unroll
    for (int i = 0; i < 2; i++)
        #pragma unroll
        for (int j = 0; j < 2; j++)
            wmma::fill_fragment(acc[i][j], 0.0f);

    constexpr int KT = K >> 4;

    auto stage = [&](int buf, int k0) {
        __half* As = smh + buf * LN_ASTRIDE;
        __half* Bs = smh + LN_BBASE + buf * BSTRIDE_H;
        if (tid < 128) {
            int r = tid >> 1, q = tid & 1;
            int gm = row0 + r;
            const __half* srcp = A + (size_t)gm * K + k0 + q * 8;
            uint32_t d = (uint32_t)__cvta_generic_to_shared(&As[r * 24 + q * 8]);
            cp16(d, srcp, gm < M);
        }
        {
            int r = tid >> 4, q = tid & 15;
            const __half* srcp = B + (size_t)(k0 + r) * NN + q * 8;
            uint32_t d = (uint32_t)__cvta_generic_to_shared(&Bs[r * 136 + q * 8]);
            cp16(d, srcp, true);
        }
        asm volatile("cp.async.commit_group;");
    };

    stage(0, 0);
    stage(1, 16);
    stage(2, 32);

    for (int kt = 0; kt < KT; kt++) {
        if (kt + 3 < KT) asm volatile("cp.async.wait_group 2;");
        else             asm volatile("cp.async.wait_group 0;");
        __syncthreads();

        int buf = kt & 3;
        const __half* As = smh + buf * LN_ASTRIDE;
        const __half* Bs = smh + LN_BBASE + buf * BSTRIDE_H;
        wmma::fragment<wmma::matrix_a, 16, 16, 16, __half, wmma::row_major> a[2];
        wmma::fragment<wmma::matrix_b, 16, 16, 16, __half, wmma::row_major> b[2];
        #pragma unroll
        for (int i = 0; i < 2; i++)
            wmma::load_matrix_sync(a[i], As + (wm * 32 + i * 16) * 24, 24);
        #pragma unroll
        for (int j = 0; j < 2; j++)
            wmma::load_matrix_sync(b[j], Bs + wn * 32 + j * 16, 136);
        #pragma unroll
        for (int i = 0; i < 2; i++)
            #pragma unroll
            for (int j = 0; j < 2; j++)
                wmma::mma_sync(acc[i][j], a[i], b[j], acc[i][j]);

        if (kt + 3 < KT) stage((kt + 3) & 3, (kt + 3) << 4);
    }

    // fused bias + layernorm epilogue (single 64-row phase)
    __syncthreads();
    #pragma unroll
    for (int i = 0; i < 2; i++)
        #pragma unroll
        for (int j = 0; j < 2; j++)
            wmma::store_matrix_sync(
                smf + (size_t)(wm * 32 + i * 16) * 132 + wn * 32 + j * 16,
                acc[i][j], 132, wmma::mem_row_major);
    __syncthreads();

    float4 bnv = ((const float4*)bn)[lane];
    float4 ggv = ((const float4*)lng)[lane];
    float4 bbv = ((const float4*)lnb)[lane];
    #pragma unroll
    for (int rr = 0; rr < 8; rr++) {
        int lr = warp * 8 + rr;
        int gm = row0 + lr;
        float4 v = *(const float4*)(smf + (size_t)lr * 132 + lane * 4);
        v.x += bnv.x; v.y += bnv.y; v.z += bnv.z; v.w += bnv.w;
        float s = v.x + v.y + v.z + v.w;
        #pragma unroll
        for (int o = 16; o; o >>= 1) s += __shfl_xor_sync(0xffffffffu, s, o);
        float mu = s * (1.f / 128.f);
        float dx = v.x - mu, dy = v.y - mu, dz = v.z - mu, dw = v.w - mu;
        float q = dx * dx + dy * dy + dz * dz + dw * dw;
        #pragma unroll
        for (int o = 16; o; o >>= 1) q += __shfl_xor_sync(0xffffffffu, q, o);
        float rstd = rsqrtf(q * (1.f / 128.f) + 1e-5f);
        float4 o4;
        o4.x = dx * rstd * ggv.x + bbv.x;
        o4.y = dy * rstd * ggv.y + bbv.y;
        o4.z = dz * rstd * ggv.z + bbv.z;
        o4.w = dw * rstd * ggv.w + bbv.w;
        if (gm < M) {
            if (doHalf) {
                uint2 u = pack_h4(o4.x, o4.y, o4.z, o4.w);
                *(uint2*)(CH + (size_t)gm * NN + lane * 4) = u;
            } else {
                *(float4*)(C0 + (size_t)gm * NN + lane * 4) = o4;
            }
        }
    }
}

// ------- aggregation: smem edge staging, one exp per (edge,head) -------------------
// block = node (128 threads); fast path deg<=128, per-warp fallback otherwise
__global__ __launch_bounds__(128) void k_agg(const float* __restrict__ bgat) {
    __shared__ int   s_src[128];
    __shared__ float s_v[4][128];    // [head][edge] - conflict-free per-warp

    int n = blockIdx.x;
    int tid = threadIdx.x;
    int h = tid >> 5, lane = tid & 31;
    int beg = g_rowptr[n], end = g_rowptr[n + 1];
    int deg = end - beg;

    float4 acc = make_float4(0.f, 0.f, 0.f, 0.f);
    float iz;
    const __half* fbase = g_featH + h * Dd + lane * 4;

    if (deg <= 128) {
        if (tid < deg) {
            int s = g_csrsrc[beg + tid];
            s_src[tid] = s;
            float4 el = *(const float4*)(g_el + s * 4);
            float4 er = *(const float4*)(g_er + n * 4);
            float v0 = el.x + er.x; v0 = v0 > 0.f ? v0 : 0.2f * v0;
            float v1 = el.y + er.y; v1 = v1 > 0.f ? v1 : 0.2f * v1;
            float v2 = el.z + er.z; v2 = v2 > 0.f ? v2 : 0.2f * v2;
            float v3 = el.w + er.w; v3 = v3 > 0.f ? v3 : 0.2f * v3;
            s_v[0][tid] = v0; s_v[1][tid] = v1;
            s_v[2][tid] = v2; s_v[3][tid] = v3;
        }
        __syncthreads();

        float m = -1e30f;
        for (int e = lane; e < deg; e += 32) m = fmaxf(m, s_v[h][e]);
        #pragma unroll
        for (int o = 16; o; o >>= 1) m = fmaxf(m, __shfl_xor_sync(0xffffffffu, m, o));

        float z = 0.f;
        for (int e = lane; e < deg; e += 32) {
            float w = __expf(s_v[h][e] - m);
            s_v[h][e] = w;
            z += w;
        }
        #pragma unroll
        for (int o = 16; o; o >>= 1) z += __shfl_xor_sync(0xffffffffu, z, o);
        iz = 1.f / fmaxf(z, 1e-20f);
        __syncwarp();

        // gather: smem weight + one 8B feat load per edge, 8-way unrolled
        int e = 0;
        for (; e + 8 <= deg; e += 8) {
            int ss[8]; float ww[8]; uint2 uu[8];
            #pragma unroll
            for (int q = 0; q < 8; q++) { ss[q] = s_src[e + q]; ww[q] = s_v[h][e + q]; }
            #pragma unroll
            for (int q = 0; q < 8; q++) uu[q] = *(const uint2*)(fbase + (size_t)ss[q] * HDd);
            #pragma unroll
            for (int q = 0; q < 8; q++) {
                float2 a = __half22float2(*(__half2*)&uu[q].x);
                float2 b = __half22float2(*(__half2*)&uu[q].y);
                acc.x += ww[q] * a.x; acc.y += ww[q] * a.y;
                acc.z += ww[q] * b.x; acc.w += ww[q] * b.y;
            }
        }
        for (; e < deg; e++) {
            int s = s_src[e];
            float w = s_v[h][e];
            uint2 u = *(const uint2*)(fbase + (size_t)s * HDd);
            float2 a = __half22float2(*(__half2*)&u.x), b = __half22float2(*(__half2*)&u.y);
            acc.x += w * a.x; acc.y += w * a.y; acc.z += w * b.x; acc.w += w * b.y;
        }
    } else {
        // fallback: per-warp two-pass (any degree)
        float ern = g_er[n * 4 + h];
        float m = -1e30f, z = 0.f;
        for (int e = beg + lane; e < end; e += 32) {
            int s = g_csrsrc[e];
            float v = g_el[s * 4 + h] + ern;
            v = v > 0.f ? v : 0.2f * v;
            float M = fmaxf(m, v);
            z = z * __expf(m - M) + __expf(v - M);
            m = M;
        }
        #pragma unroll
        for (int o = 16; o; o >>= 1) {
            float mo = __shfl_xor_sync(0xffffffffu, m, o);
            float zo = __shfl_xor_sync(0xffffffffu, z, o);
            float M = fmaxf(m, mo);
            z = z * __expf(m - M) + zo * __expf(mo - M);
            m = M;
        }
        iz = 1.f / fmaxf(z, 1e-20f);
        for (int e = beg; e < end; e++) {
            int s = g_csrsrc[e];
            float v = g_el[s * 4 + h] + ern;
            v = v > 0.f ? v : 0.2f * v;
            float w = __expf(v - m);
            uint2 u = *(const uint2*)(fbase + (size_t)s * HDd);
            float2 a = __half22float2(*(__half2*)&u.x), b = __half22float2(*(__half2*)&u.y);
            acc.x += w * a.x; acc.y += w * a.y; acc.z += w * b.x; acc.w += w * b.y;
        }
    }

    size_t off = (size_t)n * HDd + h * Dd + lane * 4;
    uint2 ru = *(const uint2*)(g_resR + off);
    float2 ra = __half22float2(*(__half2*)&ru.x), rb = __half22float2(*(__half2*)&ru.y);
    float4 bg = *(const float4*)(bgat + h * Dd + lane * 4);
    float4 o;
    o.x = acc.x * iz + ra.x + bg.x;
    o.y = acc.y * iz + ra.y + bg.y;
    o.z = acc.z * iz + rb.x + bg.z;
    o.w = acc.w * iz + rb.y + bg.w;
    o.x = o.x > 0.f ? o.x : 0.01f * o.x;
    o.y = o.y > 0.f ? o.y : 0.01f * o.y;
    o.z = o.z > 0.f ? o.z : 0.01f * o.z;
    o.w = o.w > 0.f ? o.w : 0.01f * o.w;
    uint2 u = pack_h4(o.x, o.y, o.z, o.w);
    *(uint2*)(g_resH + off) = u;
}

// ---------------- launch ----------------
extern "C" void kernel_launch(void* const* d_in, const int* in_sizes, int n_in,
                              void* d_out, int out_size)
{
    const float* features = (const float*)d_in[0];
    const int*   src      = (const int*)  d_in[1];
    const int*   dst      = (const int*)  d_in[2];
    const float* W_fc     = (const float*)d_in[3];
    const float* attn_l   = (const float*)d_in[4];
    const float* attn_r   = (const float*)d_in[5];
    const float* W_res    = (const float*)d_in[6];
    const float* b_gat    = (const float*)d_in[7];
    const float* W_nrm    = (const float*)d_in[8];
    const float* b_nrm    = (const float*)d_in[9];
    const float* ln_g     = (const float*)d_in[10];
    const float* ln_b     = (const float*)d_in[11];
    float* out = (float*)d_out;

    __half *xh0, *xhA, *xhB, *wh, *resH;
    cudaGetSymbolAddress((void**)&xh0,  g_xh0);
    cudaGetSymbolAddress((void**)&xhA,  g_xhA);
    cudaGetSymbolAddress((void**)&xhB,  g_xhB);
    cudaGetSymbolAddress((void**)&wh,   g_wh);
    cudaGetSymbolAddress((void**)&resH, g_resH);

    // preamble (fp16 convert + zero), count, scan -> dual GEMM is launch #4 for ncu
    k_pre<<<(NFEAT + 255) / 256, 256>>>(W_fc, W_res, W_nrm, features);
    k_count<<<(Ee + 255) / 256, 256>>>(dst);
    k_scan<<<1, 1024>>>();

    const int gy = (Nn + 127) / 128;   // 391
    const int gln = (Nn + 63) / 64;    // 782

    const __half* xin = xh0;
    for (int l = 0; l < Ll; l++) {
        const __half* Wf = wh + (size_t)l * WSZ;
        const __half* Wr = wh + (size_t)(Ll + l) * WSZ;
        const __half* Wn = wh + (size_t)(2 * Ll + l) * WSZ;

        // fused: featH(fp16) + el/er = xin@Wf ; resR(fp16) = xin@Wr
        dim3 g1(2 * (HDd / 128), gy);
        gemm_h<Dd, HDd / 128><<<g1, 256>>>(
            xin, Wf, Wr, Nn, attn_l + l * Hh * Dd, attn_r + l * Hh * Dd);

        if (l == 0) k_fill<<<(Ee + 255) / 256, 256>>>(src, dst);

        k_agg<<<Nn, 128>>>(b_gat + l * HDd);

        // xout = layernorm(resH @ Wn + b_nrm), fused LN epilogue, 64-row tiles
        if (l == Ll - 1) {
            gemm_ln<HDd><<<gln, 256>>>(
                resH, Wn, out, nullptr, Nn,
                b_nrm + l * Dd, ln_g + l * Dd, ln_b + l * Dd, 0);
        } else {
            __half* xout = (l & 1) ? xhB : xhA;
            gemm_ln<HDd><<<gln, 256>>>(
                resH, Wn, nullptr, xout, Nn,
                b_nrm + l * Dd, ln_g + l * Dd, ln_b + l * Dd, 1);
            xin = xout;
        }
    }
}

// round 13
// speedup vs baseline: 2.4359x; 1.0662x over previous
#include <cuda_runtime.h>
#include <cuda_fp16.h>
#include <mma.h>
#include <cstdint>
using namespace nvcuda;

#define Nn 50000
#define Ee 800000
#define Hh 4
#define Dd 128
#define HDd 512
#define Ll 4

#define WSZ (Dd * HDd)          // 65536 per weight matrix
#define NWEIGHT (3 * Ll * WSZ)  // 786432
#define NFEAT (Nn * Dd)         // 6.4M

// gemm_h (dual) smem, BK=32, 3-stage (halves): 3 A bufs (128x40) + 3 B bufs (32x136)
#define ASTRIDE_H 5120          // 128*40
#define BBASE_H   15360         // 3*ASTRIDE_H
#define BSTRIDE_H 4352          // 32*136
#define SMBYTES_H ((BBASE_H + 3 * BSTRIDE_H) * 2)   // 56832 B (dynamic)

// gemm_ln smem, BK=32, 3-stage: 3 A bufs (64x40) + 3 B bufs (32x136) = 41472 B static
#define LN_ASTRIDE 2560         // 64*40
#define LN_BBASE   7680         // 3*LN_ASTRIDE
#define LN_SMBYTES ((LN_BBASE + 3 * BSTRIDE_H) * 2) // 41472

// ---------------- scratch (static device memory; no allocations) ----------------
__device__ __align__(16) __half g_featH[(size_t)Nn * HDd];  // fp16 feat (k_agg payload)
__device__ __align__(16) __half g_resR [(size_t)Nn * HDd];  // fp16 x@Wr (k_agg residual)
__device__ __align__(16) __half g_resH [(size_t)Nn * HDd];  // fp16 k_agg out (GEMM2 A)
__device__ __align__(16) float  g_el[Nn * Hh];
__device__ __align__(16) float  g_er[Nn * Hh];
__device__ __align__(16) __half g_xh0[(size_t)Nn * Dd];     // fp16 features
__device__ __align__(16) __half g_xhA[(size_t)Nn * Dd];
__device__ __align__(16) __half g_xhB[(size_t)Nn * Dd];
__device__ __align__(16) __half g_wh[NWEIGHT];              // fp16 weights
__device__ int g_deg[Nn];
__device__ int g_rowptr[Nn + 1];
__device__ int g_cursor[Nn];
__device__ int g_csrsrc[Ee];

// ---------------- preamble: convert weights+features to fp16, zero deg -------------
__global__ void k_pre(const float* __restrict__ Wf, const float* __restrict__ Wr,
                      const float* __restrict__ Wn, const float* __restrict__ feats)
{
    int i = blockIdx.x * blockDim.x + threadIdx.x;
    if (i < NFEAT) g_xh0[i] = __float2half_rn(feats[i]);
    if (i < Ll * WSZ) {
        g_wh[i]                = __float2half_rn(Wf[i]);
        g_wh[Ll * WSZ + i]     = __float2half_rn(Wr[i]);
        g_wh[2 * Ll * WSZ + i] = __float2half_rn(Wn[i]);
    }
    if (i < Nn) g_deg[i] = 0;
}

__global__ void k_count(const int* __restrict__ dst) {
    int i = blockIdx.x * blockDim.x + threadIdx.x;
    if (i < Ee) atomicAdd(&g_deg[dst[i]], 1);
}

// single-block warp-shuffle scan: 4 elems/thread, 4096/chunk, carry across chunks
__global__ void k_scan() {
    __shared__ int wsum[32];
    __shared__ int carry;
    int t = threadIdx.x, lane = t & 31, wid = t >> 5;
    if (t == 0) { carry = 0; g_rowptr[0] = 0; }
    __syncthreads();
    for (int base = 0; base < Nn; base += 4096) {
        int idx = base + t * 4;
        int v0 = (idx + 0 < Nn) ? g_deg[idx + 0] : 0;
        int v1 = (idx + 1 < Nn) ? g_deg[idx + 1] : 0;
        int v2 = (idx + 2 < Nn) ? g_deg[idx + 2] : 0;
        int v3 = (idx + 3 < Nn) ? g_deg[idx + 3] : 0;
        int s0 = v0, s1 = s0 + v1, s2 = s1 + v2, s3 = s2 + v3;
        int incl = s3;
        #pragma unroll
        for (int o = 1; o < 32; o <<= 1) {
            int x = __shfl_up_sync(0xffffffffu, incl, o);
            if (lane >= o) incl += x;
        }
        if (lane == 31) wsum[wid] = incl;
        __syncthreads();
        if (wid == 0) {
            int x = wsum[lane];
            #pragma unroll
            for (int o = 1; o < 32; o <<= 1) {
                int y = __shfl_up_sync(0xffffffffu, x, o);
                if (lane >= o) x += y;
            }
            wsum[lane] = x;
        }
        __syncthreads();
        int pre = carry + (wid ? wsum[wid - 1] : 0) + (incl - s3);
        if (idx + 0 < Nn) { g_rowptr[idx + 1] = pre + s0; g_cursor[idx + 0] = pre; }
        if (idx + 1 < Nn) { g_rowptr[idx + 2] = pre + s1; g_cursor[idx + 1] = pre + s0; }
        if (idx + 2 < Nn) { g_rowptr[idx + 3] = pre + s2; g_cursor[idx + 2] = pre + s1; }
        if (idx + 3 < Nn) { g_rowptr[idx + 4] = pre + s3; g_cursor[idx + 3] = pre + s2; }
        __syncthreads();
        if (t == 0) carry += wsum[31];
        __syncthreads();
    }
}

__global__ void k_fill(const int* __restrict__ src, const int* __restrict__ dst) {
    int i = blockIdx.x * blockDim.x + threadIdx.x;
    if (i < Ee) {
        int p = atomicAdd(&g_cursor[dst[i]], 1);
        g_csrsrc[p] = src[i];
    }
}

// ---------------- cp.async helper ----------------
__device__ __forceinline__ void cp16(uint32_t dst, const void* src, bool pred) {
    int sz = pred ? 16 : 0;
    asm volatile("cp.async.cg.shared.global [%0], [%1], 16, %2;\n"
                 :: "r"(dst), "l"(src), "r"(sz));
}

__device__ __forceinline__ uint2 pack_h4(float x, float y, float z, float w) {
    __half2 h0 = __floats2half2_rn(x, y);
    __half2 h1 = __floats2half2_rn(z, w);
    uint2 u;
    u.x = *reinterpret_cast<unsigned*>(&h0);
    u.y = *reinterpret_cast<unsigned*>(&h1);
    return u;
}

// ---------------- dual fp16 GEMM, CTA 128x128, BK=32, 3-stage ring ---------------
// Both halves epilogue via smem -> fp16 stores (guarded).
// feat half (bx<TPH): also computes attn el/er (head h == bx).
template<int K, int TPH>
__global__ __launch_bounds__(256) void gemm_h(
    const __half* __restrict__ A,
    const __half* __restrict__ B0, const __half* __restrict__ B1,
    int M, const float* __restrict__ p0, const float* __restrict__ p1)
{
    constexpr int NN = TPH * 128;
    extern __shared__ __half smh[];
    float* smf = reinterpret_cast<float*>(smh);

    const int tid = threadIdx.x;
    const int warp = tid >> 5;
    const int lane = tid & 31;
    const int wm = warp & 1, wn = warp >> 1;
    const int row0 = blockIdx.y * 128;

    int bx = blockIdx.x;
    bool isFeatHalf = (bx < TPH);
    const __half* B = B0;
    if (!isFeatHalf) { bx -= TPH; B = B1; }
    const int col0 = bx * 128;

    wmma::fragment<wmma::accumulator, 16, 16, 16, float> acc[4][2];
    #pragma unroll
    for (int i = 0; i < 4; i++)
        #pragma unroll
        for (int j = 0; j < 2; j++)
            wmma::fill_fragment(acc[i][j], 0.0f);

    constexpr int KT = K >> 5;   // BK=32

    auto stage = [&](int buf, int k0) {
        __half* As = smh + buf * ASTRIDE_H;
        __half* Bs = smh + BBASE_H + buf * BSTRIDE_H;
        #pragma unroll
        for (int p = 0; p < 2; p++) {   // A: 128 rows x 32 halves = 512 x 16B
            int c = tid + p * 256;
            int r = c >> 2, q = c & 3;
            int gm = row0 + r;
            const __half* srcp = A + (size_t)gm * K + k0 + q * 8;
            uint32_t d = (uint32_t)__cvta_generic_to_shared(&As[r * 40 + q * 8]);
            cp16(d, srcp, gm < M);
        }
        #pragma unroll
        for (int p = 0; p < 2; p++) {   // B: 32 rows x 128 halves = 512 x 16B
            int c = tid + p * 256;
            int r = c >> 4, q = c & 15;
            const __half* srcp = B + (size_t)(k0 + r) * NN + col0 + q * 8;
            uint32_t d = (uint32_t)__cvta_generic_to_shared(&Bs[r * 136 + q * 8]);
            cp16(d, srcp, true);
        }
        asm volatile("cp.async.commit_group;");
    };

    stage(0, 0);
    stage(1, 32);

    #pragma unroll
    for (int kt = 0; kt < KT; kt++) {
        if (kt + 2 < KT) asm volatile("cp.async.wait_group 1;");
        else             asm volatile("cp.async.wait_group 0;");
        __syncthreads();

        const int buf = kt % 3;
        const __half* As = smh + buf * ASTRIDE_H;
        const __half* Bs = smh + BBASE_H + buf * BSTRIDE_H;
        #pragma unroll
        for (int kk = 0; kk < 2; kk++) {
            wmma::fragment<wmma::matrix_a, 16, 16, 16, __half, wmma::row_major> a[4];
            wmma::fragment<wmma::matrix_b, 16, 16, 16, __half, wmma::row_major> b[2];
            #pragma unroll
            for (int i = 0; i < 4; i++)
                wmma::load_matrix_sync(a[i], As + (wm * 64 + i * 16) * 40 + kk * 16, 40);
            #pragma unroll
            for (int j = 0; j < 2; j++)
                wmma::load_matrix_sync(b[j], Bs + (kk * 16) * 136 + wn * 32 + j * 16, 136);
            #pragma unroll
            for (int i = 0; i < 4; i++)
                #pragma unroll
                for (int j = 0; j < 2; j++)
                    wmma::mma_sync(acc[i][j], a[i], b[j], acc[i][j]);
        }

        if (kt + 2 < KT) stage((kt + 2) % 3, (kt + 2) << 5);
    }

    // epilogue: acc -> smem (two 64-row phases) -> fp16 global (+ el/er on feat half)
    float* sC = smf;   // 64 x 132 floats
    float4 alv, arv;
    if (isFeatHalf) {
        alv = *(const float4*)(p0 + col0 + lane * 4);
        arv = *(const float4*)(p1 + col0 + lane * 4);
    }
    __half* outbase = isFeatHalf ? g_featH : g_resR;
    __syncthreads();
    #pragma unroll
    for (int p = 0; p < 2; p++) {
        if (wm == p) {
            #pragma unroll
            for (int i = 0; i < 4; i++)
                #pragma unroll
                for (int j = 0; j < 2; j++)
                    wmma::store_matrix_sync(
                        sC + (size_t)(i * 16) * 132 + wn * 32 + j * 16,
                        acc[i][j], 132, wmma::mem_row_major);
        }
        __syncthreads();
        #pragma unroll
        for (int rr = 0; rr < 8; rr++) {
            int lr = warp * 8 + rr;
            int gm = row0 + p * 64 + lr;
            float4 v = *(const float4*)(sC + (size_t)lr * 132 + lane * 4);
            bool valid = gm < M;
            if (valid) {
                uint2 u = pack_h4(v.x, v.y, v.z, v.w);
                *(uint2*)(outbase + (size_t)gm * HDd + col0 + lane * 4) = u;
            }
            if (isFeatHalf) {
                float sl = v.x * alv.x + v.y * alv.y + v.z * alv.z + v.w * alv.w;
                float sr = v.x * arv.x + v.y * arv.y + v.z * arv.z + v.w * arv.w;
                #pragma unroll
                for (int o = 16; o; o >>= 1) {
                    sl += __shfl_xor_sync(0xffffffffu, sl, o);
                    sr += __shfl_xor_sync(0xffffffffu, sr, o);
                }
                if (lane == 0 && valid) {
                    g_el[gm * Hh + bx] = sl;
                    g_er[gm * Hh + bx] = sr;
                }
            }
        }
        __syncthreads();
    }
}

// ---------------- GEMM2 + LN: CTA 64x128, BK=32, 3-stage, warp 32x32 --------------
template<int K>
__global__ __launch_bounds__(256) void gemm_ln(
    const __half* __restrict__ A, const __half* __restrict__ B,
    float* __restrict__ C0, __half* __restrict__ CH, int M,
    const float* __restrict__ bn, const float* __restrict__ lng,
    const float* __restrict__ lnb, int doHalf)
{
    constexpr int NN = 128;
    __shared__ __align__(16) char smraw[LN_SMBYTES];
    __half* smh = reinterpret_cast<__half*>(smraw);
    float* smf = reinterpret_cast<float*>(smraw);

    const int tid = threadIdx.x;
    const int warp = tid >> 5;
    const int lane = tid & 31;
    const int wm = warp & 1, wn = warp >> 1;
    const int row0 = blockIdx.x * 64;

    wmma::fragment<wmma::accumulator, 16, 16, 16, float> acc[2][2];
    #pragma unroll
    for (int i = 0; i < 2; i++)
        #pragma unroll
        for (int j = 0; j < 2; j++)
            wmma::fill_fragment(acc[i][j], 0.0f);

    constexpr int KT = K >> 5;

    auto stage = [&](int buf, int k0) {
        __half* As = smh + buf * LN_ASTRIDE;
        __half* Bs = smh + LN_BBASE + buf * BSTRIDE_H;
        {   // A: 64 rows x 32 halves = 256 x 16B (1/thread)
            int r = tid >> 2, q = tid & 3;
            int gm = row0 + r;
            const __half* srcp = A + (size_t)gm * K + k0 + q * 8;
            uint32_t d = (uint32_t)__cvta_generic_to_shared(&As[r * 40 + q * 8]);
            cp16(d, srcp, gm < M);
        }
        #pragma unroll
        for (int p = 0; p < 2; p++) {   // B: 32 rows x 128 halves = 512 x 16B
            int c = tid + p * 256;
            int r = c >> 4, q = c & 15;
            const __half* srcp = B + (size_t)(k0 + r) * NN + q * 8;
            uint32_t d = (uint32_t)__cvta_generic_to_shared(&Bs[r * 136 + q * 8]);
            cp16(d, srcp, true);
        }
        asm volatile("cp.async.commit_group;");
    };

    stage(0, 0);
    stage(1, 32);

    #pragma unroll
    for (int kt = 0; kt < KT; kt++) {
        if (kt + 2 < KT) asm volatile("cp.async.wait_group 1;");
        else             asm volatile("cp.async.wait_group 0;");
        __syncthreads();

        const int buf = kt % 3;
        const __half* As = smh + buf * LN_ASTRIDE;
        const __half* Bs = smh + LN_BBASE + buf * BSTRIDE_H;
        #pragma unroll
        for (int kk = 0; kk < 2; kk++) {
            wmma::fragment<wmma::matrix_a, 16, 16, 16, __half, wmma::row_major> a[2];
            wmma::fragment<wmma::matrix_b, 16, 16, 16, __half, wmma::row_major> b[2];
            #pragma unroll
            for (int i = 0; i < 2; i++)
                wmma::load_matrix_sync(a[i], As + (wm * 32 + i * 16) * 40 + kk * 16, 40);
            #pragma unroll
            for (int j = 0; j < 2; j++)
                wmma::load_matrix_sync(b[j], Bs + (kk * 16) * 136 + wn * 32 + j * 16, 136);
            #pragma unroll
            for (int i = 0; i < 2; i++)
                #pragma unroll
                for (int j = 0; j < 2; j++)
                    wmma::mma_sync(acc[i][j], a[i], b[j], acc[i][j]);
        }

        if (kt + 2 < KT) stage((kt + 2) % 3, (kt + 2) << 5);
    }

    // fused bias + layernorm epilogue (single 64-row phase)
    __syncthreads();
    #pragma unroll
    for (int i = 0; i < 2; i++)
        #pragma unroll
        for (int j = 0; j < 2; j++)
            wmma::store_matrix_sync(
                smf + (size_t)(wm * 32 + i * 16) * 132 + wn * 32 + j * 16,
                acc[i][j], 132, wmma::mem_row_major);
    __syncthreads();

    float4 bnv = ((const float4*)bn)[lane];
    float4 ggv = ((const float4*)lng)[lane];
    float4 bbv = ((const float4*)lnb)[lane];
    #pragma unroll
    for (int rr = 0; rr < 8; rr++) {
        int lr = warp * 8 + rr;
        int gm = row0 + lr;
        float4 v = *(const float4*)(smf + (size_t)lr * 132 + lane * 4);
        v.x += bnv.x; v.y += bnv.y; v.z += bnv.z; v.w += bnv.w;
        float s = v.x + v.y + v.z + v.w;
        #pragma unroll
        for (int o = 16; o; o >>= 1) s += __shfl_xor_sync(0xffffffffu, s, o);
        float mu = s * (1.f / 128.f);
        float dx = v.x - mu, dy = v.y - mu, dz = v.z - mu, dw = v.w - mu;
        float q = dx * dx + dy * dy + dz * dz + dw * dw;
        #pragma unroll
        for (int o = 16; o; o >>= 1) q += __shfl_xor_sync(0xffffffffu, q, o);
        float rstd = rsqrtf(q * (1.f / 128.f) + 1e-5f);
        float4 o4;
        o4.x = dx * rstd * ggv.x + bbv.x;
        o4.y = dy * rstd * ggv.y + bbv.y;
        o4.z = dz * rstd * ggv.z + bbv.z;
        o4.w = dw * rstd * ggv.w + bbv.w;
        if (gm < M) {
            if (doHalf) {
                uint2 u = pack_h4(o4.x, o4.y, o4.z, o4.w);
                *(uint2*)(CH + (size_t)gm * NN + lane * 4) = u;
            } else {
                *(float4*)(C0 + (size_t)gm * NN + lane * 4) = o4;
            }
        }
    }
}

// ------- aggregation: smem edge staging, one exp per (edge,head) -------------------
// block = node (128 threads); fast path deg<=128, per-warp fallback otherwise
__global__ __launch_bounds__(128) void k_agg(const float* __restrict__ bgat) {
    __shared__ int   s_src[128];
    __shared__ float s_v[4][128];    // [head][edge] - conflict-free per-warp

    int n = blockIdx.x;
    int tid = threadIdx.x;
    int h = tid >> 5, lane = tid & 31;
    int beg = g_rowptr[n], end = g_rowptr[n + 1];
    int deg = end - beg;

    float4 acc = make_float4(0.f, 0.f, 0.f, 0.f);
    float iz;
    const __half* fbase = g_featH + h * Dd + lane * 4;

    if (deg <= 128) {
        if (tid < deg) {
            int s = g_csrsrc[beg + tid];
            s_src[tid] = s;
            float4 el = *(const float4*)(g_el + s * 4);
            float4 er = *(const float4*)(g_er + n * 4);
            float v0 = el.x + er.x; v0 = v0 > 0.f ? v0 : 0.2f * v0;
            float v1 = el.y + er.y; v1 = v1 > 0.f ? v1 : 0.2f * v1;
            float v2 = el.z + er.z; v2 = v2 > 0.f ? v2 : 0.2f * v2;
            float v3 = el.w + er.w; v3 = v3 > 0.f ? v3 : 0.2f * v3;
            s_v[0][tid] = v0; s_v[1][tid] = v1;
            s_v[2][tid] = v2; s_v[3][tid] = v3;
        }
        __syncthreads();

        float m = -1e30f;
        for (int e = lane; e < deg; e += 32) m = fmaxf(m, s_v[h][e]);
        #pragma unroll
        for (int o = 16; o; o >>= 1) m = fmaxf(m, __shfl_xor_sync(0xffffffffu, m, o));

        float z = 0.f;
        for (int e = lane; e < deg; e += 32) {
            float w = __expf(s_v[h][e] - m);
            s_v[h][e] = w;
            z += w;
        }
        #pragma unroll
        for (int o = 16; o; o >>= 1) z += __shfl_xor_sync(0xffffffffu, z, o);
        iz = 1.f / fmaxf(z, 1e-20f);
        __syncwarp();

        // gather: smem weight + one 8B feat load per edge, 8-way unrolled
        int e = 0;
        for (; e + 8 <= deg; e += 8) {
            int ss[8]; float ww[8]; uint2 uu[8];
            #pragma unroll
            for (int q = 0; q < 8; q++) { ss[q] = s_src[e + q]; ww[q] = s_v[h][e + q]; }
            #pragma unroll
            for (int q = 0; q < 8; q++) uu[q] = *(const uint2*)(fbase + (size_t)ss[q] * HDd);
            #pragma unroll
            for (int q = 0; q < 8; q++) {
                float2 a = __half22float2(*(__half2*)&uu[q].x);
                float2 b = __half22float2(*(__half2*)&uu[q].y);
                acc.x += ww[q] * a.x; acc.y += ww[q] * a.y;
                acc.z += ww[q] * b.x; acc.w += ww[q] * b.y;
            }
        }
        for (; e < deg; e++) {
            int s = s_src[e];
            float w = s_v[h][e];
            uint2 u = *(const uint2*)(fbase + (size_t)s * HDd);
            float2 a = __half22float2(*(__half2*)&u.x), b = __half22float2(*(__half2*)&u.y);
            acc.x += w * a.x; acc.y += w * a.y; acc.z += w * b.x; acc.w += w * b.y;
        }
    } else {
        // fallback: per-warp two-pass (any degree)
        float ern = g_er[n * 4 + h];
        float m = -1e30f, z = 0.f;
        for (int e = beg + lane; e < end; e += 32) {
            int s = g_csrsrc[e];
            float v = g_el[s * 4 + h] + ern;
            v = v > 0.f ? v : 0.2f * v;
            float M = fmaxf(m, v);
            z = z * __expf(m - M) + __expf(v - M);
            m = M;
        }
        #pragma unroll
        for (int o = 16; o; o >>= 1) {
            float mo = __shfl_xor_sync(0xffffffffu, m, o);
            float zo = __shfl_xor_sync(0xffffffffu, z, o);
            float M = fmaxf(m, mo);
            z = z * __expf(m - M) + zo * __expf(mo - M);
            m = M;
        }
        iz = 1.f / fmaxf(z, 1e-20f);
        for (int e = beg; e < end; e++) {
            int s = g_csrsrc[e];
            float v = g_el[s * 4 + h] + ern;
            v = v > 0.f ? v : 0.2f * v;
            float w = __expf(v - m);
            uint2 u = *(const uint2*)(fbase + (size_t)s * HDd);
            float2 a = __half22float2(*(__half2*)&u.x), b = __half22float2(*(__half2*)&u.y);
            acc.x += w * a.x; acc.y += w * a.y; acc.z += w * b.x; acc.w += w * b.y;
        }
    }

    size_t off = (size_t)n * HDd + h * Dd + lane * 4;
    uint2 ru = *(const uint2*)(g_resR + off);
    float2 ra = __half22float2(*(__half2*)&ru.x), rb = __half22float2(*(__half2*)&ru.y);
    float4 bg = *(const float4*)(bgat + h * Dd + lane * 4);
    float4 o;
    o.x = acc.x * iz + ra.x + bg.x;
    o.y = acc.y * iz + ra.y + bg.y;
    o.z = acc.z * iz + rb.x + bg.z;
    o.w = acc.w * iz + rb.y + bg.w;
    o.x = o.x > 0.f ? o.x : 0.01f * o.x;
    o.y = o.y > 0.f ? o.y : 0.01f * o.y;
    o.z = o.z > 0.f ? o.z : 0.01f * o.z;
    o.w = o.w > 0.f ? o.w : 0.01f * o.w;
    uint2 u = pack_h4(o.x, o.y, o.z, o.w);
    *(uint2*)(g_resH + off) = u;
}

// ---------------- launch ----------------
extern "C" void kernel_launch(void* const* d_in, const int* in_sizes, int n_in,
                              void* d_out, int out_size)
{
    const float* features = (const float*)d_in[0];
    const int*   src      = (const int*)  d_in[1];
    const int*   dst      = (const int*)  d_in[2];
    const float* W_fc     = (const float*)d_in[3];
    const float* attn_l   = (const float*)d_in[4];
    const float* attn_r   = (const float*)d_in[5];
    const float* W_res    = (const float*)d_in[6];
    const float* b_gat    = (const float*)d_in[7];
    const float* W_nrm    = (const float*)d_in[8];
    const float* b_nrm    = (const float*)d_in[9];
    const float* ln_g     = (const float*)d_in[10];
    const float* ln_b     = (const float*)d_in[11];
    float* out = (float*)d_out;

    __half *xh0, *xhA, *xhB, *wh, *resH;
    cudaGetSymbolAddress((void**)&xh0,  g_xh0);
    cudaGetSymbolAddress((void**)&xhA,  g_xhA);
    cudaGetSymbolAddress((void**)&xhB,  g_xhB);
    cudaGetSymbolAddress((void**)&wh,   g_wh);
    cudaGetSymbolAddress((void**)&resH, g_resH);

    static int smemSet = 0;
    if (!smemSet) {
        cudaFuncSetAttribute(gemm_h<Dd, HDd / 128>,
                             cudaFuncAttributeMaxDynamicSharedMemorySize, SMBYTES_H);
        smemSet = 1;
    }

    // preamble (fp16 convert + zero), count, scan -> dual GEMM is launch #4 for ncu
    k_pre<<<(NFEAT + 255) / 256, 256>>>(W_fc, W_res, W_nrm, features);
    k_count<<<(Ee + 255) / 256, 256>>>(dst);
    k_scan<<<1, 1024>>>();

    const int gy = (Nn + 127) / 128;   // 391
    const int gln = (Nn + 63) / 64;    // 782

    const __half* xin = xh0;
    for (int l = 0; l < Ll; l++) {
        const __half* Wf = wh + (size_t)l * WSZ;
        const __half* Wr = wh + (size_t)(Ll + l) * WSZ;
        const __half* Wn = wh + (size_t)(2 * Ll + l) * WSZ;

        // fused: featH(fp16) + el/er = xin@Wf ; resR(fp16) = xin@Wr
        dim3 g1(2 * (HDd / 128), gy);
        gemm_h<Dd, HDd / 128><<<g1, 256, SMBYTES_H>>>(
            xin, Wf, Wr, Nn, attn_l + l * Hh * Dd, attn_r + l * Hh * Dd);

        if (l == 0) k_fill<<<(Ee + 255) / 256, 256>>>(src, dst);

        k_agg<<<Nn, 128>>>(b_gat + l * HDd);

        // xout = layernorm(resH @ Wn + b_nrm), fused LN epilogue, 64-row tiles
        if (l == Ll - 1) {
            gemm_ln<HDd><<<gln, 256>>>(
                resH, Wn, out, nullptr, Nn,
                b_nrm + l * Dd, ln_g + l * Dd, ln_b + l * Dd, 0);
        } else {
            __half* xout = (l & 1) ? xhB : xhA;
            gemm_ln<HDd><<<gln, 256>>>(
                resH, Wn, nullptr, xout, Nn,
                b_nrm + l * Dd, ln_g + l * Dd, ln_b + l * Dd, 1);
            xin = xout;
        }
    }
}